// round 8
// baseline (speedup 1.0000x reference)
#include <cuda_runtime.h>
#include <cuda_bf16.h>
#include <cstdint>

typedef unsigned int       u32;
typedef unsigned long long u64;

#define ROWS 1024
#define AGG  260

__device__ float g_Mfold[256 * 256];   // [x][h*64+e], 1/sqrt(D) folded
__device__ float g_qk[ROWS * 256];
__device__ u32   g_WVh[4096];          // W_V hi bf16x2, [c*32 + e/2]
__device__ u32   g_WVl[4096];          // W_V lo bf16x2
__device__ float g_WRt[AGG * 128];     // W_R transposed [k][o]
__device__ float g_multi[ROWS * AGG];

// ---------------- f32x2 helpers ----------------
__device__ __forceinline__ u64 pack2(float a, float b) {
    u64 r; asm("mov.b64 %0, {%1, %2};" : "=l"(r) : "f"(a), "f"(b)); return r;
}
__device__ __forceinline__ void unpack2(u64 v, float& a, float& b) {
    asm("mov.b64 {%0, %1}, %2;" : "=f"(a), "=f"(b) : "l"(v));
}
__device__ __forceinline__ u64 fma2(u64 a, u64 b, u64 c) {
    u64 d; asm("fma.rn.f32x2 %0, %1, %2, %3;" : "=l"(d) : "l"(a), "l"(b), "l"(c));
    return d;
}

// ---------------- warp mma: m16n8k16 bf16, D/C f32, accumulate in-place ----
__device__ __forceinline__ void mma16816(float* d, const u32* a, const u32* b) {
    asm volatile(
        "mma.sync.aligned.m16n8k16.row.col.f32.bf16.bf16.f32 "
        "{%0,%1,%2,%3}, {%4,%5,%6,%7}, {%8,%9}, {%0,%1,%2,%3};"
        : "+f"(d[0]), "+f"(d[1]), "+f"(d[2]), "+f"(d[3])
        : "r"(a[0]), "r"(a[1]), "r"(a[2]), "r"(a[3]), "r"(b[0]), "r"(b[1]));
}

// rotation swizzle: row m (32 u32), logical col c -> conflict-free banks
#define BP(m, c) ((m) * 32 + (((c) + ((m) << 2)) & 31))

// =================== prep: Mfold + W_V split (R4 exact) + W_R transpose ======
__global__ __launch_bounds__(256)
void prep_kernel(const float* __restrict__ WQ, const float* __restrict__ WK,
                 const float* __restrict__ WV, const float* __restrict__ WR) {
    const int b = blockIdx.x, tid = threadIdx.x;
    if (b < 256) {
        __shared__ float wq[128];
        if (tid < 128) wq[tid] = WQ[tid * 256 + b];
        __syncthreads();
        const int h = tid >> 6, e = tid & 63;
        float acc = 0.f;
        #pragma unroll 8
        for (int d = 0; d < 32; d++)
            acc += wq[h * 32 + d] * WK[(h * 32 + d) * 64 + e];
        g_Mfold[b * 256 + tid] = acc * 0.1767766952966369f;  // 1/sqrt(32)
    } else if (b < 260) {
        #pragma unroll
        for (int r = 0; r < 4; r++) {
            int idx = (b - 256) * 1024 + r * 256 + tid;  // < 4096
            int c = idx >> 5, e0 = (idx & 31) * 2;
            float x0 = WV[c * 64 + e0], x1 = WV[c * 64 + e0 + 1];
            __nv_bfloat16 h0 = __float2bfloat16(x0), h1 = __float2bfloat16(x1);
            __nv_bfloat16 l0 = __float2bfloat16(x0 - __bfloat162float(h0));
            __nv_bfloat16 l1 = __float2bfloat16(x1 - __bfloat162float(h1));
            __nv_bfloat162 hp = __halves2bfloat162(h0, h1);
            __nv_bfloat162 lp = __halves2bfloat162(l0, l1);
            g_WVh[idx] = *(u32*)&hp;
            g_WVl[idx] = *(u32*)&lp;
        }
    } else {
        int idx = (b - 260) * 256 + tid;             // < 33280 = 260*128
        int k = idx >> 7, o = idx & 127;
        g_WRt[idx] = WR[o * 260 + k];
    }
}

// =================== qk = h_x @ Mfold (R4 exact) ===================
__global__ __launch_bounds__(256)
void qk_kernel(const float* __restrict__ hx) {
    __shared__ float sx[8][256];
    const int tid = threadIdx.x, r0 = blockIdx.x * 8;
    for (int i = tid; i < 2048; i += 256) sx[i >> 8][i & 255] = hx[r0 * 256 + i];
    __syncthreads();
    float a[8] = {0.f, 0.f, 0.f, 0.f, 0.f, 0.f, 0.f, 0.f};
    #pragma unroll 4
    for (int x = 0; x < 256; x++) {
        float mf = g_Mfold[x * 256 + tid];
        #pragma unroll
        for (int k = 0; k < 8; k++) a[k] += sx[k][x] * mf;
    }
    #pragma unroll
    for (int k = 0; k < 8; k++) g_qk[(r0 + k) * 256 + tid] = a[k];
}

// =================== main (R4 exact) ===================
#define DYN_SMEM (2 * 32768)

__global__ __launch_bounds__(256, 2)
void main_kernel(const float* __restrict__ h_e, const float* __restrict__ h_m) {
    extern __shared__ u32 dynu[];
    __shared__ __align__(16) float s_qk[256];
    __shared__ float s_attn[1024];
    __shared__ float s_asum[4];
    __shared__ float s_ps[2][128];
    __shared__ float s_pm[2][128];

    u32* s_bhi = dynu;           // [256 m][32 u32], rotation-swizzled
    u32* s_blo = dynu + 8192;

    const int bn   = blockIdx.x;
    const int tid  = threadIdx.x;
    const int wid  = tid >> 5;
    const int lane = tid & 31;
    const int gid  = lane >> 2;
    const int tid4 = lane & 3;
    const int cg   = wid & 3;    // c-group = head
    const int mh   = wid >> 2;   // m-half
    const int cbase = cg * 32;

    if (tid < 4) s_asum[tid] = 0.f;

    // ---- convert h_e -> bf16 hi/lo swizzled smem ----
    const float4* src = (const float4*)(h_e + (size_t)bn * 16384);
    #pragma unroll
    for (int it = 0; it < 16; it++) {
        int flat = it * 256 + tid;
        int m = flat >> 4, c0 = (flat & 15) * 2;
        float4 v = src[flat];
        __nv_bfloat16 b0 = __float2bfloat16(v.x), b1 = __float2bfloat16(v.y);
        __nv_bfloat16 b2 = __float2bfloat16(v.z), b3 = __float2bfloat16(v.w);
        __nv_bfloat16 l0 = __float2bfloat16(v.x - __bfloat162float(b0));
        __nv_bfloat16 l1 = __float2bfloat16(v.y - __bfloat162float(b1));
        __nv_bfloat16 l2 = __float2bfloat16(v.z - __bfloat162float(b2));
        __nv_bfloat16 l3 = __float2bfloat16(v.w - __bfloat162float(b3));
        __nv_bfloat162 h01 = __halves2bfloat162(b0, b1);
        __nv_bfloat162 h23 = __halves2bfloat162(b2, b3);
        __nv_bfloat162 q01 = __halves2bfloat162(l0, l1);
        __nv_bfloat162 q23 = __halves2bfloat162(l2, l3);
        s_bhi[BP(m, c0)]     = *(u32*)&h01;
        s_bhi[BP(m, c0 + 1)] = *(u32*)&h23;
        s_blo[BP(m, c0)]     = *(u32*)&q01;
        s_blo[BP(m, c0 + 1)] = *(u32*)&q23;
    }
    s_qk[tid] = g_qk[bn * 256 + tid];
    const float maskv = h_m[bn];

    // ---- A fragments (W_V hi/lo) -> registers, 2 c-tiles per warp ----
    u32 Ah[2][16], Al[2][16];
    #pragma unroll
    for (int j = 0; j < 2; j++) {
        int r0 = cbase + j * 16 + gid;
        #pragma unroll
        for (int ks = 0; ks < 4; ks++) {
            int b0 = r0 * 32 + ks * 8 + tid4;
            int b1 = (r0 + 8) * 32 + ks * 8 + tid4;
            Ah[j][ks * 4 + 0] = g_WVh[b0];
            Ah[j][ks * 4 + 1] = g_WVh[b1];
            Ah[j][ks * 4 + 2] = g_WVh[b0 + 4];
            Ah[j][ks * 4 + 3] = g_WVh[b1 + 4];
            Al[j][ks * 4 + 0] = g_WVl[b0];
            Al[j][ks * 4 + 1] = g_WVl[b1];
            Al[j][ks * 4 + 2] = g_WVl[b0 + 4];
            Al[j][ks * 4 + 3] = g_WVl[b1 + 4];
        }
    }
    __syncthreads();

    // ---- scores + softmax over heads (thread = m) ----
    {
        const int m = tid;
        u64 acc0 = 0ull, acc1 = 0ull, acc2 = 0ull, acc3 = 0ull;
        const u64* qp = (const u64*)s_qk;
        #pragma unroll 8
        for (int j = 0; j < 32; j++) {
            int ep = (j + m) & 31;                   // bank-spread order
            int pi = BP(m, ep);
            u32 h2 = s_bhi[pi], l2 = s_blo[pi];
            float2 fh = __bfloat1622float2(*(__nv_bfloat162*)&h2);
            float2 fl = __bfloat1622float2(*(__nv_bfloat162*)&l2);
            u64 he = pack2(fh.x + fl.x, fh.y + fl.y);
            acc0 = fma2(he, qp[ep],      acc0);
            acc1 = fma2(he, qp[32 + ep], acc1);
            acc2 = fma2(he, qp[64 + ep], acc2);
            acc3 = fma2(he, qp[96 + ep], acc3);
        }
        float x, y, s0, s1, s2, s3;
        unpack2(acc0, x, y); s0 = x + y;
        unpack2(acc1, x, y); s1 = x + y;
        unpack2(acc2, x, y); s2 = x + y;
        unpack2(acc3, x, y); s3 = x + y;
        if (maskv == 0.f) {
            const float ninf = __int_as_float(0xff800000);
            s0 = s1 = s2 = s3 = ninf;
        }
        float mx = fmaxf(fmaxf(s0, s1), fmaxf(s2, s3));
        float e0 = __expf(s0 - mx), e1 = __expf(s1 - mx);
        float e2 = __expf(s2 - mx), e3 = __expf(s3 - mx);
        float r  = 1.f / (e0 + e1 + e2 + e3);
        float a0 = e0 * r, a1 = e1 * r, a2 = e2 * r, a3 = e3 * r;
        s_attn[m]       = a0;
        s_attn[256 + m] = a1;
        s_attn[512 + m] = a2;
        s_attn[768 + m] = a3;
        float t0 = a0, t1 = a1, t2 = a2, t3 = a3;
        #pragma unroll
        for (int off = 16; off; off >>= 1) {
            t0 += __shfl_xor_sync(0xffffffffu, t0, off);
            t1 += __shfl_xor_sync(0xffffffffu, t1, off);
            t2 += __shfl_xor_sync(0xffffffffu, t2, off);
            t3 += __shfl_xor_sync(0xffffffffu, t3, off);
        }
        if (lane == 0) {
            atomicAdd(&s_asum[0], t0);
            atomicAdd(&s_asum[1], t1);
            atomicAdd(&s_asum[2], t2);
            atomicAdd(&s_asum[3], t3);
        }
    }
    __syncthreads();

    // ---- mainloop: 16 m-tiles x 2 c-tiles, 3-term bf16 mma + fused epilogue ----
    const float ninf = __int_as_float(0xff800000);
    float sum0 = 0.f, sum1 = 0.f, sum2 = 0.f, sum3 = 0.f;
    float mx0 = ninf, mx1 = ninf, mx2 = ninf, mx3 = ninf;
    const float* ap = s_attn + cg * 256;

    for (int t = 0; t < 16; t++) {
        const int mbase = mh * 128 + t * 8;
        const int mrow  = mbase + gid;
        u32 Bh[8], Bl[8];
        #pragma unroll
        for (int ks = 0; ks < 4; ks++) {
            int c0 = ks * 8 + tid4;
            Bh[ks * 2]     = s_bhi[BP(mrow, c0)];
            Bh[ks * 2 + 1] = s_bhi[BP(mrow, c0 + 4)];
            Bl[ks * 2]     = s_blo[BP(mrow, c0)];
            Bl[ks * 2 + 1] = s_blo[BP(mrow, c0 + 4)];
        }
        float2 at = *(const float2*)(ap + mbase + 2 * tid4);
        #pragma unroll
        for (int j = 0; j < 2; j++) {
            float d[4] = {0.f, 0.f, 0.f, 0.f};
            #pragma unroll
            for (int ks = 0; ks < 4; ks++) {
                mma16816(d, &Ah[j][ks * 4], &Bh[ks * 2]);
                mma16816(d, &Ah[j][ks * 4], &Bl[ks * 2]);
                mma16816(d, &Al[j][ks * 4], &Bh[ks * 2]);
            }
            float w0 = at.x * d[0], w1 = at.y * d[1];
            float w2 = at.x * d[2], w3 = at.y * d[3];
            if (j == 0) {
                sum0 += w0 + w1; sum1 += w2 + w3;
                mx0 = fmaxf(mx0, fmaxf(w0, w1));
                mx1 = fmaxf(mx1, fmaxf(w2, w3));
            } else {
                sum2 += w0 + w1; sum3 += w2 + w3;
                mx2 = fmaxf(mx2, fmaxf(w0, w1));
                mx3 = fmaxf(mx3, fmaxf(w2, w3));
            }
        }
    }

    // reduce across quad (tid4)
    #pragma unroll
    for (int off = 1; off <= 2; off <<= 1) {
        sum0 += __shfl_xor_sync(0xffffffffu, sum0, off);
        sum1 += __shfl_xor_sync(0xffffffffu, sum1, off);
        sum2 += __shfl_xor_sync(0xffffffffu, sum2, off);
        sum3 += __shfl_xor_sync(0xffffffffu, sum3, off);
        mx0 = fmaxf(mx0, __shfl_xor_sync(0xffffffffu, mx0, off));
        mx1 = fmaxf(mx1, __shfl_xor_sync(0xffffffffu, mx1, off));
        mx2 = fmaxf(mx2, __shfl_xor_sync(0xffffffffu, mx2, off));
        mx3 = fmaxf(mx3, __shfl_xor_sync(0xffffffffu, mx3, off));
    }
    if (tid4 == 0) {
        s_ps[mh][cbase + gid]      = sum0;  s_pm[mh][cbase + gid]      = mx0;
        s_ps[mh][cbase + gid + 8]  = sum1;  s_pm[mh][cbase + gid + 8]  = mx1;
        s_ps[mh][cbase + gid + 16] = sum2;  s_pm[mh][cbase + gid + 16] = mx2;
        s_ps[mh][cbase + gid + 24] = sum3;  s_pm[mh][cbase + gid + 24] = mx3;
    }
    __syncthreads();

    if (tid < 128) {
        const int c = tid, h = c >> 5, d = c & 31;
        float s  = s_ps[0][c] + s_ps[1][c];
        float mx = fmaxf(s_pm[0][c], s_pm[1][c]);
        float asum = s_asum[h] + 1e-8f;
        float* mrow = g_multi + (size_t)bn * AGG + h * 65;
        mrow[d]      = s / asum;
        if (d == 0) mrow[32] = asum;
        mrow[33 + d] = mx;
    }
}

// =================== out v4: coalesced transposed-W_R streaming ===============
// grid 256 x 256 threads; 4 rows per block; thread = (o in [0,128), kh in {0,1})
__global__ __launch_bounds__(256)
void out_kernel(float* __restrict__ out) {
    __shared__ __align__(16) float smt[AGG][4];   // multi^T for this block's 4 rows
    __shared__ float s_part[4][128];

    const int tid  = threadIdx.x;
    const int row0 = blockIdx.x * 4;

    for (int i = tid; i < 4 * AGG; i += 256) {
        int r = i / AGG, k = i - r * AGG;
        smt[k][r] = g_multi[(size_t)(row0 + r) * AGG + k];
    }
    __syncthreads();

    const int o  = tid & 127;
    const int kh = tid >> 7;
    const int kb = kh * 130;
    const float* wr = g_WRt + kb * 128 + o;   // coalesced across o
    float a0 = 0.f, a1 = 0.f, a2 = 0.f, a3 = 0.f;
    #pragma unroll 5
    for (int k = 0; k < 130; k++) {
        float w  = wr[k * 128];
        float4 m = *(const float4*)smt[kb + k];
        a0 += m.x * w; a1 += m.y * w; a2 += m.z * w; a3 += m.w * w;
    }
    if (kh == 0) {
        s_part[0][o] = a0; s_part[1][o] = a1;
        s_part[2][o] = a2; s_part[3][o] = a3;
    }
    __syncthreads();
    if (kh == 1) {
        out[(size_t)(row0 + 0) * 128 + o] = s_part[0][o] + a0;
        out[(size_t)(row0 + 1) * 128 + o] = s_part[1][o] + a1;
        out[(size_t)(row0 + 2) * 128 + o] = s_part[2][o] + a2;
        out[(size_t)(row0 + 3) * 128 + o] = s_part[3][o] + a3;
    }
}

// =================== launch ===================
extern "C" void kernel_launch(void* const* d_in, const int* in_sizes, int n_in,
                              void* d_out, int out_size) {
    (void)in_sizes; (void)n_in; (void)out_size;
    const float* h_x = (const float*)d_in[0];
    const float* h_e = (const float*)d_in[1];
    const float* h_m = (const float*)d_in[2];
    const float* W_Q = (const float*)d_in[3];
    const float* W_K = (const float*)d_in[4];
    const float* W_V = (const float*)d_in[5];
    const float* W_R = (const float*)d_in[6];
    float* out = (float*)d_out;

    cudaFuncSetAttribute(main_kernel,
                         cudaFuncAttributeMaxDynamicSharedMemorySize, DYN_SMEM);

    prep_kernel<<<390, 256>>>(W_Q, W_K, W_V, W_R);
    qk_kernel<<<128, 256>>>(h_x);
    main_kernel<<<ROWS, 256, DYN_SMEM>>>(h_e, h_m);
    out_kernel<<<256, 256>>>(out);
}

// round 9
// speedup vs baseline: 1.1657x; 1.1657x over previous
#include <cuda_runtime.h>
#include <cuda_bf16.h>
#include <cstdint>

typedef unsigned int       u32;
typedef unsigned long long u64;

#define ROWS 1024
#define AGG  260

__device__ float g_Mfold[256 * 256];   // [x][h*64+e], 1/sqrt(D) folded
__device__ float g_qk[ROWS * 256];
__device__ u32   g_WVh[4096];          // W_V hi bf16x2, [c*32 + e/2]
__device__ u32   g_WVl[4096];          // W_V lo bf16x2
__device__ float g_multi[ROWS * AGG];

// ---------------- f32x2 helpers ----------------
__device__ __forceinline__ u64 pack2(float a, float b) {
    u64 r; asm("mov.b64 %0, {%1, %2};" : "=l"(r) : "f"(a), "f"(b)); return r;
}
__device__ __forceinline__ void unpack2(u64 v, float& a, float& b) {
    asm("mov.b64 {%0, %1}, %2;" : "=f"(a), "=f"(b) : "l"(v));
}
__device__ __forceinline__ u64 fma2(u64 a, u64 b, u64 c) {
    u64 d; asm("fma.rn.f32x2 %0, %1, %2, %3;" : "=l"(d) : "l"(a), "l"(b), "l"(c));
    return d;
}

// ---------------- warp mma: m16n8k16 bf16, D/C f32, accumulate in-place ----
__device__ __forceinline__ void mma16816(float* d, const u32* a, const u32* b) {
    asm volatile(
        "mma.sync.aligned.m16n8k16.row.col.f32.bf16.bf16.f32 "
        "{%0,%1,%2,%3}, {%4,%5,%6,%7}, {%8,%9}, {%0,%1,%2,%3};"
        : "+f"(d[0]), "+f"(d[1]), "+f"(d[2]), "+f"(d[3])
        : "r"(a[0]), "r"(a[1]), "r"(a[2]), "r"(a[3]), "r"(b[0]), "r"(b[1]));
}

// rotation swizzle: row m (32 u32), logical col c -> conflict-free banks
#define BP(m, c) ((m) * 32 + (((c) + ((m) << 2)) & 31))

// =================== prep: Mfold + W_V bf16 hi/lo split (R7 exact) ===========
__global__ __launch_bounds__(256)
void prep_kernel(const float* __restrict__ WQ, const float* __restrict__ WK,
                 const float* __restrict__ WV) {
    const int b = blockIdx.x, tid = threadIdx.x;
    if (b < 256) {
        __shared__ float wq[128];
        if (tid < 128) wq[tid] = WQ[tid * 256 + b];
        __syncthreads();
        const int h = tid >> 6, e = tid & 63;
        float acc = 0.f;
        #pragma unroll 8
        for (int d = 0; d < 32; d++)
            acc += wq[h * 32 + d] * WK[(h * 32 + d) * 64 + e];
        g_Mfold[b * 256 + tid] = acc * 0.1767766952966369f;  // 1/sqrt(32)
    } else {
        #pragma unroll
        for (int r = 0; r < 4; r++) {
            int idx = (b - 256) * 1024 + r * 256 + tid;  // < 4096
            int c = idx >> 5, e0 = (idx & 31) * 2;
            float x0 = WV[c * 64 + e0], x1 = WV[c * 64 + e0 + 1];
            __nv_bfloat16 h0 = __float2bfloat16(x0), h1 = __float2bfloat16(x1);
            __nv_bfloat16 l0 = __float2bfloat16(x0 - __bfloat162float(h0));
            __nv_bfloat16 l1 = __float2bfloat16(x1 - __bfloat162float(h1));
            __nv_bfloat162 hp = __halves2bfloat162(h0, h1);
            __nv_bfloat162 lp = __halves2bfloat162(l0, l1);
            g_WVh[idx] = *(u32*)&hp;
            g_WVl[idx] = *(u32*)&lp;
        }
    }
}

// =================== qk = h_x @ Mfold (R7 exact) ===================
__global__ __launch_bounds__(256)
void qk_kernel(const float* __restrict__ hx) {
    __shared__ float sx[8][256];
    const int tid = threadIdx.x, r0 = blockIdx.x * 8;
    for (int i = tid; i < 2048; i += 256) sx[i >> 8][i & 255] = hx[r0 * 256 + i];
    __syncthreads();
    float a[8] = {0.f, 0.f, 0.f, 0.f, 0.f, 0.f, 0.f, 0.f};
    #pragma unroll 4
    for (int x = 0; x < 256; x++) {
        float mf = g_Mfold[x * 256 + tid];
        #pragma unroll
        for (int k = 0; k < 8; k++) a[k] += sx[k][x] * mf;
    }
    #pragma unroll
    for (int k = 0; k < 8; k++) g_qk[(r0 + k) * 256 + tid] = a[k];
}

// =================== main: 2-term split (A*Bh via Ah*Bh + Al*Bh) =============
#define DYN_SMEM (2 * 32768)

__global__ __launch_bounds__(256, 2)
void main_kernel(const float* __restrict__ h_e, const float* __restrict__ h_m) {
    extern __shared__ u32 dynu[];
    __shared__ __align__(16) float s_qk[256];
    __shared__ float s_attn[1024];
    __shared__ float s_asum[4];
    __shared__ float s_ps[2][128];
    __shared__ float s_pm[2][128];

    u32* s_bhi = dynu;           // [256 m][32 u32], rotation-swizzled
    u32* s_blo = dynu + 8192;    // lo half: used by fp32 score reconstruction

    const int bn   = blockIdx.x;
    const int tid  = threadIdx.x;
    const int wid  = tid >> 5;
    const int lane = tid & 31;
    const int gid  = lane >> 2;
    const int tid4 = lane & 3;
    const int cg   = wid & 3;    // c-group = head
    const int mh   = wid >> 2;   // m-half
    const int cbase = cg * 32;

    if (tid < 4) s_asum[tid] = 0.f;

    // ---- convert h_e -> bf16 hi/lo swizzled smem ----
    const float4* src = (const float4*)(h_e + (size_t)bn * 16384);
    #pragma unroll
    for (int it = 0; it < 16; it++) {
        int flat = it * 256 + tid;
        int m = flat >> 4, c0 = (flat & 15) * 2;
        float4 v = src[flat];
        __nv_bfloat16 b0 = __float2bfloat16(v.x), b1 = __float2bfloat16(v.y);
        __nv_bfloat16 b2 = __float2bfloat16(v.z), b3 = __float2bfloat16(v.w);
        __nv_bfloat16 l0 = __float2bfloat16(v.x - __bfloat162float(b0));
        __nv_bfloat16 l1 = __float2bfloat16(v.y - __bfloat162float(b1));
        __nv_bfloat16 l2 = __float2bfloat16(v.z - __bfloat162float(b2));
        __nv_bfloat16 l3 = __float2bfloat16(v.w - __bfloat162float(b3));
        __nv_bfloat162 h01 = __halves2bfloat162(b0, b1);
        __nv_bfloat162 h23 = __halves2bfloat162(b2, b3);
        __nv_bfloat162 q01 = __halves2bfloat162(l0, l1);
        __nv_bfloat162 q23 = __halves2bfloat162(l2, l3);
        s_bhi[BP(m, c0)]     = *(u32*)&h01;
        s_bhi[BP(m, c0 + 1)] = *(u32*)&h23;
        s_blo[BP(m, c0)]     = *(u32*)&q01;
        s_blo[BP(m, c0 + 1)] = *(u32*)&q23;
    }
    s_qk[tid] = g_qk[bn * 256 + tid];
    const float maskv = h_m[bn];

    // ---- A fragments (W_V hi/lo) -> registers, 2 c-tiles per warp ----
    u32 Ah[2][16], Al[2][16];
    #pragma unroll
    for (int j = 0; j < 2; j++) {
        int r0 = cbase + j * 16 + gid;
        #pragma unroll
        for (int ks = 0; ks < 4; ks++) {
            int b0 = r0 * 32 + ks * 8 + tid4;
            int b1 = (r0 + 8) * 32 + ks * 8 + tid4;
            Ah[j][ks * 4 + 0] = g_WVh[b0];
            Ah[j][ks * 4 + 1] = g_WVh[b1];
            Ah[j][ks * 4 + 2] = g_WVh[b0 + 4];
            Ah[j][ks * 4 + 3] = g_WVh[b1 + 4];
            Al[j][ks * 4 + 0] = g_WVl[b0];
            Al[j][ks * 4 + 1] = g_WVl[b1];
            Al[j][ks * 4 + 2] = g_WVl[b0 + 4];
            Al[j][ks * 4 + 3] = g_WVl[b1 + 4];
        }
    }
    __syncthreads();

    // ---- scores + softmax over heads (thread = m); full fp32 via hi+lo ----
    {
        const int m = tid;
        u64 acc0 = 0ull, acc1 = 0ull, acc2 = 0ull, acc3 = 0ull;
        const u64* qp = (const u64*)s_qk;
        #pragma unroll 8
        for (int j = 0; j < 32; j++) {
            int ep = (j + m) & 31;                   // bank-spread order
            int pi = BP(m, ep);
            u32 h2 = s_bhi[pi], l2 = s_blo[pi];
            float2 fh = __bfloat1622float2(*(__nv_bfloat162*)&h2);
            float2 fl = __bfloat1622float2(*(__nv_bfloat162*)&l2);
            u64 he = pack2(fh.x + fl.x, fh.y + fl.y);
            acc0 = fma2(he, qp[ep],      acc0);
            acc1 = fma2(he, qp[32 + ep], acc1);
            acc2 = fma2(he, qp[64 + ep], acc2);
            acc3 = fma2(he, qp[96 + ep], acc3);
        }
        float x, y, s0, s1, s2, s3;
        unpack2(acc0, x, y); s0 = x + y;
        unpack2(acc1, x, y); s1 = x + y;
        unpack2(acc2, x, y); s2 = x + y;
        unpack2(acc3, x, y); s3 = x + y;
        if (maskv == 0.f) {
            const float ninf = __int_as_float(0xff800000);
            s0 = s1 = s2 = s3 = ninf;
        }
        float mx = fmaxf(fmaxf(s0, s1), fmaxf(s2, s3));
        float e0 = __expf(s0 - mx), e1 = __expf(s1 - mx);
        float e2 = __expf(s2 - mx), e3 = __expf(s3 - mx);
        float r  = 1.f / (e0 + e1 + e2 + e3);
        float a0 = e0 * r, a1 = e1 * r, a2 = e2 * r, a3 = e3 * r;
        s_attn[m]       = a0;
        s_attn[256 + m] = a1;
        s_attn[512 + m] = a2;
        s_attn[768 + m] = a3;
        float t0 = a0, t1 = a1, t2 = a2, t3 = a3;
        #pragma unroll
        for (int off = 16; off; off >>= 1) {
            t0 += __shfl_xor_sync(0xffffffffu, t0, off);
            t1 += __shfl_xor_sync(0xffffffffu, t1, off);
            t2 += __shfl_xor_sync(0xffffffffu, t2, off);
            t3 += __shfl_xor_sync(0xffffffffu, t3, off);
        }
        if (lane == 0) {
            atomicAdd(&s_asum[0], t0);
            atomicAdd(&s_asum[1], t1);
            atomicAdd(&s_asum[2], t2);
            atomicAdd(&s_asum[3], t3);
        }
    }
    __syncthreads();

    // ---- mainloop: 16 m-tiles x 2 c-tiles, 2-term (Ah+Al)*Bh ----
    const float ninf = __int_as_float(0xff800000);
    float sum0 = 0.f, sum1 = 0.f, sum2 = 0.f, sum3 = 0.f;
    float mx0 = ninf, mx1 = ninf, mx2 = ninf, mx3 = ninf;
    const float* ap = s_attn + cg * 256;

    for (int t = 0; t < 16; t++) {
        const int mbase = mh * 128 + t * 8;
        const int mrow  = mbase + gid;
        u32 Bh[8];
        #pragma unroll
        for (int ks = 0; ks < 4; ks++) {
            int c0 = ks * 8 + tid4;
            Bh[ks * 2]     = s_bhi[BP(mrow, c0)];
            Bh[ks * 2 + 1] = s_bhi[BP(mrow, c0 + 4)];
        }
        float2 at = *(const float2*)(ap + mbase + 2 * tid4);
        #pragma unroll
        for (int j = 0; j < 2; j++) {
            float d[4] = {0.f, 0.f, 0.f, 0.f};
            #pragma unroll
            for (int ks = 0; ks < 4; ks++) {
                mma16816(d, &Ah[j][ks * 4], &Bh[ks * 2]);
                mma16816(d, &Al[j][ks * 4], &Bh[ks * 2]);
            }
            float w0 = at.x * d[0], w1 = at.y * d[1];
            float w2 = at.x * d[2], w3 = at.y * d[3];
            if (j == 0) {
                sum0 += w0 + w1; sum1 += w2 + w3;
                mx0 = fmaxf(mx0, fmaxf(w0, w1));
                mx1 = fmaxf(mx1, fmaxf(w2, w3));
            } else {
                sum2 += w0 + w1; sum3 += w2 + w3;
                mx2 = fmaxf(mx2, fmaxf(w0, w1));
                mx3 = fmaxf(mx3, fmaxf(w2, w3));
            }
        }
    }

    // reduce across quad (tid4)
    #pragma unroll
    for (int off = 1; off <= 2; off <<= 1) {
        sum0 += __shfl_xor_sync(0xffffffffu, sum0, off);
        sum1 += __shfl_xor_sync(0xffffffffu, sum1, off);
        sum2 += __shfl_xor_sync(0xffffffffu, sum2, off);
        sum3 += __shfl_xor_sync(0xffffffffu, sum3, off);
        mx0 = fmaxf(mx0, __shfl_xor_sync(0xffffffffu, mx0, off));
        mx1 = fmaxf(mx1, __shfl_xor_sync(0xffffffffu, mx1, off));
        mx2 = fmaxf(mx2, __shfl_xor_sync(0xffffffffu, mx2, off));
        mx3 = fmaxf(mx3, __shfl_xor_sync(0xffffffffu, mx3, off));
    }
    if (tid4 == 0) {
        s_ps[mh][cbase + gid]      = sum0;  s_pm[mh][cbase + gid]      = mx0;
        s_ps[mh][cbase + gid + 8]  = sum1;  s_pm[mh][cbase + gid + 8]  = mx1;
        s_ps[mh][cbase + gid + 16] = sum2;  s_pm[mh][cbase + gid + 16] = mx2;
        s_ps[mh][cbase + gid + 24] = sum3;  s_pm[mh][cbase + gid + 24] = mx3;
    }
    __syncthreads();

    if (tid < 128) {
        const int c = tid, h = c >> 5, d = c & 31;
        float s  = s_ps[0][c] + s_ps[1][c];
        float mx = fmaxf(s_pm[0][c], s_pm[1][c]);
        float asum = s_asum[h] + 1e-8f;
        float* mrow = g_multi + (size_t)bn * AGG + h * 65;
        mrow[d]      = s / asum;
        if (d == 0) mrow[32] = asum;
        mrow[33 + d] = mx;
    }
}

// =================== out v3 (R7 exact, measured best) ===================
__global__ __launch_bounds__(256)
void out_kernel(const float* __restrict__ W_R, float* __restrict__ out) {
    __shared__ __align__(16) float smt[AGG][4];   // multi^T for this block's 4 rows
    __shared__ float s_part[4][128];

    const int tid  = threadIdx.x;
    const int row0 = blockIdx.x * 4;

    for (int i = tid; i < 4 * AGG; i += 256) {
        int r = i / AGG, k = i - r * AGG;
        smt[k][r] = g_multi[(size_t)(row0 + r) * AGG + k];
    }
    __syncthreads();

    const int o  = tid & 127;
    const int kh = tid >> 7;
    const int kb = kh * 130;
    const float2* wr = (const float2*)(W_R + o * AGG + kb);  // 8B-aligned
    float a0 = 0.f, a1 = 0.f, a2 = 0.f, a3 = 0.f;
    #pragma unroll 5
    for (int j = 0; j < 65; j++) {
        float2 w  = wr[j];
        float4 m0 = *(const float4*)smt[kb + 2 * j];
        float4 m1 = *(const float4*)smt[kb + 2 * j + 1];
        a0 += m0.x * w.x + m1.x * w.y;
        a1 += m0.y * w.x + m1.y * w.y;
        a2 += m0.z * w.x + m1.z * w.y;
        a3 += m0.w * w.x + m1.w * w.y;
    }
    if (kh == 0) {
        s_part[0][o] = a0; s_part[1][o] = a1;
        s_part[2][o] = a2; s_part[3][o] = a3;
    }
    __syncthreads();
    if (kh == 1) {
        out[(size_t)(row0 + 0) * 128 + o] = s_part[0][o] + a0;
        out[(size_t)(row0 + 1) * 128 + o] = s_part[1][o] + a1;
        out[(size_t)(row0 + 2) * 128 + o] = s_part[2][o] + a2;
        out[(size_t)(row0 + 3) * 128 + o] = s_part[3][o] + a3;
    }
}

// =================== launch ===================
extern "C" void kernel_launch(void* const* d_in, const int* in_sizes, int n_in,
                              void* d_out, int out_size) {
    (void)in_sizes; (void)n_in; (void)out_size;
    const float* h_x = (const float*)d_in[0];
    const float* h_e = (const float*)d_in[1];
    const float* h_m = (const float*)d_in[2];
    const float* W_Q = (const float*)d_in[3];
    const float* W_K = (const float*)d_in[4];
    const float* W_V = (const float*)d_in[5];
    const float* W_R = (const float*)d_in[6];
    float* out = (float*)d_out;

    cudaFuncSetAttribute(main_kernel,
                         cudaFuncAttributeMaxDynamicSharedMemorySize, DYN_SMEM);

    prep_kernel<<<260, 256>>>(W_Q, W_K, W_V);
    qk_kernel<<<128, 256>>>(h_x);
    main_kernel<<<ROWS, 256, DYN_SMEM>>>(h_e, h_m);
    out_kernel<<<256, 256>>>(W_R, out);
}

// round 10
// speedup vs baseline: 1.1927x; 1.0231x over previous
#include <cuda_runtime.h>
#include <cuda_bf16.h>
#include <cstdint>

typedef unsigned int       u32;
typedef unsigned long long u64;

#define ROWS 1024
#define AGG  260

__device__ float g_Mfold[256 * 256];   // [x][h*64+e], 1/sqrt(D) folded
__device__ float g_qk[ROWS * 256];
__device__ u32   g_WVh[4096];          // W_V hi bf16x2, [c*32 + e/2]
__device__ u32   g_WVl[4096];          // W_V lo bf16x2
__device__ float g_multi[ROWS * AGG];

// ---------------- f32x2 helpers ----------------
__device__ __forceinline__ u64 pack2(float a, float b) {
    u64 r; asm("mov.b64 %0, {%1, %2};" : "=l"(r) : "f"(a), "f"(b)); return r;
}
__device__ __forceinline__ void unpack2(u64 v, float& a, float& b) {
    asm("mov.b64 {%0, %1}, %2;" : "=f"(a), "=f"(b) : "l"(v));
}
__device__ __forceinline__ u64 fma2(u64 a, u64 b, u64 c) {
    u64 d; asm("fma.rn.f32x2 %0, %1, %2, %3;" : "=l"(d) : "l"(a), "l"(b), "l"(c));
    return d;
}

// ---------------- warp mma: m16n8k16 bf16, D/C f32, accumulate in-place ----
__device__ __forceinline__ void mma16816(float* d, const u32* a, const u32* b) {
    asm volatile(
        "mma.sync.aligned.m16n8k16.row.col.f32.bf16.bf16.f32 "
        "{%0,%1,%2,%3}, {%4,%5,%6,%7}, {%8,%9}, {%0,%1,%2,%3};"
        : "+f"(d[0]), "+f"(d[1]), "+f"(d[2]), "+f"(d[3])
        : "r"(a[0]), "r"(a[1]), "r"(a[2]), "r"(a[3]), "r"(b[0]), "r"(b[1]));
}

// rotation swizzle: row m (32 u32), logical col c -> conflict-free banks
#define BP(m, c) ((m) * 32 + (((c) + ((m) << 2)) & 31))

// =================== prep: Mfold + W_V bf16 hi/lo split (R7 exact) ===========
__global__ __launch_bounds__(256)
void prep_kernel(const float* __restrict__ WQ, const float* __restrict__ WK,
                 const float* __restrict__ WV) {
    const int b = blockIdx.x, tid = threadIdx.x;
    if (b < 256) {
        __shared__ float wq[128];
        if (tid < 128) wq[tid] = WQ[tid * 256 + b];
        __syncthreads();
        const int h = tid >> 6, e = tid & 63;
        float acc = 0.f;
        #pragma unroll 8
        for (int d = 0; d < 32; d++)
            acc += wq[h * 32 + d] * WK[(h * 32 + d) * 64 + e];
        g_Mfold[b * 256 + tid] = acc * 0.1767766952966369f;  // 1/sqrt(32)
    } else {
        #pragma unroll
        for (int r = 0; r < 4; r++) {
            int idx = (b - 256) * 1024 + r * 256 + tid;  // < 4096
            int c = idx >> 5, e0 = (idx & 31) * 2;
            float x0 = WV[c * 64 + e0], x1 = WV[c * 64 + e0 + 1];
            __nv_bfloat16 h0 = __float2bfloat16(x0), h1 = __float2bfloat16(x1);
            __nv_bfloat16 l0 = __float2bfloat16(x0 - __bfloat162float(h0));
            __nv_bfloat16 l1 = __float2bfloat16(x1 - __bfloat162float(h1));
            __nv_bfloat162 hp = __halves2bfloat162(h0, h1);
            __nv_bfloat162 lp = __halves2bfloat162(l0, l1);
            g_WVh[idx] = *(u32*)&hp;
            g_WVl[idx] = *(u32*)&lp;
        }
    }
}

// =================== qk = h_x @ Mfold (unroll 16 for MLP) ===================
__global__ __launch_bounds__(256)
void qk_kernel(const float* __restrict__ hx) {
    __shared__ float sx[8][256];
    const int tid = threadIdx.x, r0 = blockIdx.x * 8;
    for (int i = tid; i < 2048; i += 256) sx[i >> 8][i & 255] = hx[r0 * 256 + i];
    __syncthreads();
    float a[8] = {0.f, 0.f, 0.f, 0.f, 0.f, 0.f, 0.f, 0.f};
    #pragma unroll 16
    for (int x = 0; x < 256; x++) {
        float mf = g_Mfold[x * 256 + tid];
        #pragma unroll
        for (int k = 0; k < 8; k++) a[k] += sx[k][x] * mf;
    }
    #pragma unroll
    for (int k = 0; k < 8; k++) g_qk[(r0 + k) * 256 + tid] = a[k];
}

// =================== main: 2-term split, split MMA chains, STS.64 ============
#define DYN_SMEM (2 * 32768)

__global__ __launch_bounds__(256, 2)
void main_kernel(const float* __restrict__ h_e, const float* __restrict__ h_m) {
    extern __shared__ u32 dynu[];
    __shared__ __align__(16) float s_qk[256];
    __shared__ float s_attn[1024];
    __shared__ float s_asum[4];
    __shared__ float s_ps[2][128];
    __shared__ float s_pm[2][128];

    u32* s_bhi = dynu;           // [256 m][32 u32], rotation-swizzled
    u32* s_blo = dynu + 8192;    // lo half: used by fp32 score reconstruction

    const int bn   = blockIdx.x;
    const int tid  = threadIdx.x;
    const int wid  = tid >> 5;
    const int lane = tid & 31;
    const int gid  = lane >> 2;
    const int tid4 = lane & 3;
    const int cg   = wid & 3;    // c-group = head
    const int mh   = wid >> 2;   // m-half
    const int cbase = cg * 32;

    if (tid < 4) s_asum[tid] = 0.f;

    // ---- convert h_e -> bf16 hi/lo swizzled smem (STS.64) ----
    const float4* src = (const float4*)(h_e + (size_t)bn * 16384);
    #pragma unroll
    for (int it = 0; it < 16; it++) {
        int flat = it * 256 + tid;
        int m = flat >> 4, c0 = (flat & 15) * 2;
        float4 v = src[flat];
        __nv_bfloat16 b0 = __float2bfloat16(v.x), b1 = __float2bfloat16(v.y);
        __nv_bfloat16 b2 = __float2bfloat16(v.z), b3 = __float2bfloat16(v.w);
        __nv_bfloat16 l0 = __float2bfloat16(v.x - __bfloat162float(b0));
        __nv_bfloat16 l1 = __float2bfloat16(v.y - __bfloat162float(b1));
        __nv_bfloat16 l2 = __float2bfloat16(v.z - __bfloat162float(b2));
        __nv_bfloat16 l3 = __float2bfloat16(v.w - __bfloat162float(b3));
        __nv_bfloat162 h01 = __halves2bfloat162(b0, b1);
        __nv_bfloat162 h23 = __halves2bfloat162(b2, b3);
        __nv_bfloat162 q01 = __halves2bfloat162(l0, l1);
        __nv_bfloat162 q23 = __halves2bfloat162(l2, l3);
        // BP(m,c0) is even (c0,4m even; never wraps to 31) -> 8B-aligned,
        // and BP(m,c0+1) = BP(m,c0)+1 -> single STS.64
        u32 base = BP(m, c0);
        *(u64*)(s_bhi + base) = (u64)(*(u32*)&h01) | ((u64)(*(u32*)&h23) << 32);
        *(u64*)(s_blo + base) = (u64)(*(u32*)&q01) | ((u64)(*(u32*)&q23) << 32);
    }
    s_qk[tid] = g_qk[bn * 256 + tid];
    const float maskv = h_m[bn];

    // ---- A fragments (W_V hi/lo) -> registers, 2 c-tiles per warp ----
    u32 Ah[2][16], Al[2][16];
    #pragma unroll
    for (int j = 0; j < 2; j++) {
        int r0 = cbase + j * 16 + gid;
        #pragma unroll
        for (int ks = 0; ks < 4; ks++) {
            int b0 = r0 * 32 + ks * 8 + tid4;
            int b1 = (r0 + 8) * 32 + ks * 8 + tid4;
            Ah[j][ks * 4 + 0] = g_WVh[b0];
            Ah[j][ks * 4 + 1] = g_WVh[b1];
            Ah[j][ks * 4 + 2] = g_WVh[b0 + 4];
            Ah[j][ks * 4 + 3] = g_WVh[b1 + 4];
            Al[j][ks * 4 + 0] = g_WVl[b0];
            Al[j][ks * 4 + 1] = g_WVl[b1];
            Al[j][ks * 4 + 2] = g_WVl[b0 + 4];
            Al[j][ks * 4 + 3] = g_WVl[b1 + 4];
        }
    }
    __syncthreads();

    // ---- scores + softmax over heads (thread = m); full fp32 via hi+lo ----
    {
        const int m = tid;
        u64 acc0 = 0ull, acc1 = 0ull, acc2 = 0ull, acc3 = 0ull;
        const u64* qp = (const u64*)s_qk;
        #pragma unroll 8
        for (int j = 0; j < 32; j++) {
            int ep = (j + m) & 31;                   // bank-spread order
            int pi = BP(m, ep);
            u32 h2 = s_bhi[pi], l2 = s_blo[pi];
            float2 fh = __bfloat1622float2(*(__nv_bfloat162*)&h2);
            float2 fl = __bfloat1622float2(*(__nv_bfloat162*)&l2);
            u64 he = pack2(fh.x + fl.x, fh.y + fl.y);
            acc0 = fma2(he, qp[ep],      acc0);
            acc1 = fma2(he, qp[32 + ep], acc1);
            acc2 = fma2(he, qp[64 + ep], acc2);
            acc3 = fma2(he, qp[96 + ep], acc3);
        }
        float x, y, s0, s1, s2, s3;
        unpack2(acc0, x, y); s0 = x + y;
        unpack2(acc1, x, y); s1 = x + y;
        unpack2(acc2, x, y); s2 = x + y;
        unpack2(acc3, x, y); s3 = x + y;
        if (maskv == 0.f) {
            const float ninf = __int_as_float(0xff800000);
            s0 = s1 = s2 = s3 = ninf;
        }
        float mx = fmaxf(fmaxf(s0, s1), fmaxf(s2, s3));
        float e0 = __expf(s0 - mx), e1 = __expf(s1 - mx);
        float e2 = __expf(s2 - mx), e3 = __expf(s3 - mx);
        float r  = 1.f / (e0 + e1 + e2 + e3);
        float a0 = e0 * r, a1 = e1 * r, a2 = e2 * r, a3 = e3 * r;
        s_attn[m]       = a0;
        s_attn[256 + m] = a1;
        s_attn[512 + m] = a2;
        s_attn[768 + m] = a3;
        float t0 = a0, t1 = a1, t2 = a2, t3 = a3;
        #pragma unroll
        for (int off = 16; off; off >>= 1) {
            t0 += __shfl_xor_sync(0xffffffffu, t0, off);
            t1 += __shfl_xor_sync(0xffffffffu, t1, off);
            t2 += __shfl_xor_sync(0xffffffffu, t2, off);
            t3 += __shfl_xor_sync(0xffffffffu, t3, off);
        }
        if (lane == 0) {
            atomicAdd(&s_asum[0], t0);
            atomicAdd(&s_asum[1], t1);
            atomicAdd(&s_asum[2], t2);
            atomicAdd(&s_asum[3], t3);
        }
    }
    __syncthreads();

    // ---- mainloop: 16 m-tiles x 2 c-tiles; Ah/Al chains split ----
    const float ninf = __int_as_float(0xff800000);
    float sum0 = 0.f, sum1 = 0.f, sum2 = 0.f, sum3 = 0.f;
    float mx0 = ninf, mx1 = ninf, mx2 = ninf, mx3 = ninf;
    const float* ap = s_attn + cg * 256;

    for (int t = 0; t < 16; t++) {
        const int mbase = mh * 128 + t * 8;
        const int mrow  = mbase + gid;
        u32 Bh[8];
        #pragma unroll
        for (int ks = 0; ks < 4; ks++) {
            int c0 = ks * 8 + tid4;
            Bh[ks * 2]     = s_bhi[BP(mrow, c0)];
            Bh[ks * 2 + 1] = s_bhi[BP(mrow, c0 + 4)];
        }
        float2 at = *(const float2*)(ap + mbase + 2 * tid4);
        #pragma unroll
        for (int j = 0; j < 2; j++) {
            float d[4]  = {0.f, 0.f, 0.f, 0.f};
            float d2[4] = {0.f, 0.f, 0.f, 0.f};
            #pragma unroll
            for (int ks = 0; ks < 4; ks++) {
                mma16816(d,  &Ah[j][ks * 4], &Bh[ks * 2]);
                mma16816(d2, &Al[j][ks * 4], &Bh[ks * 2]);
            }
            float w0 = at.x * (d[0] + d2[0]), w1 = at.y * (d[1] + d2[1]);
            float w2 = at.x * (d[2] + d2[2]), w3 = at.y * (d[3] + d2[3]);
            if (j == 0) {
                sum0 += w0 + w1; sum1 += w2 + w3;
                mx0 = fmaxf(mx0, fmaxf(w0, w1));
                mx1 = fmaxf(mx1, fmaxf(w2, w3));
            } else {
                sum2 += w0 + w1; sum3 += w2 + w3;
                mx2 = fmaxf(mx2, fmaxf(w0, w1));
                mx3 = fmaxf(mx3, fmaxf(w2, w3));
            }
        }
    }

    // reduce across quad (tid4)
    #pragma unroll
    for (int off = 1; off <= 2; off <<= 1) {
        sum0 += __shfl_xor_sync(0xffffffffu, sum0, off);
        sum1 += __shfl_xor_sync(0xffffffffu, sum1, off);
        sum2 += __shfl_xor_sync(0xffffffffu, sum2, off);
        sum3 += __shfl_xor_sync(0xffffffffu, sum3, off);
        mx0 = fmaxf(mx0, __shfl_xor_sync(0xffffffffu, mx0, off));
        mx1 = fmaxf(mx1, __shfl_xor_sync(0xffffffffu, mx1, off));
        mx2 = fmaxf(mx2, __shfl_xor_sync(0xffffffffu, mx2, off));
        mx3 = fmaxf(mx3, __shfl_xor_sync(0xffffffffu, mx3, off));
    }
    if (tid4 == 0) {
        s_ps[mh][cbase + gid]      = sum0;  s_pm[mh][cbase + gid]      = mx0;
        s_ps[mh][cbase + gid + 8]  = sum1;  s_pm[mh][cbase + gid + 8]  = mx1;
        s_ps[mh][cbase + gid + 16] = sum2;  s_pm[mh][cbase + gid + 16] = mx2;
        s_ps[mh][cbase + gid + 24] = sum3;  s_pm[mh][cbase + gid + 24] = mx3;
    }
    __syncthreads();

    if (tid < 128) {
        const int c = tid, h = c >> 5, d = c & 31;
        float s  = s_ps[0][c] + s_ps[1][c];
        float mx = fmaxf(s_pm[0][c], s_pm[1][c]);
        float asum = s_asum[h] + 1e-8f;
        float* mrow = g_multi + (size_t)bn * AGG + h * 65;
        mrow[d]      = s / asum;
        if (d == 0) mrow[32] = asum;
        mrow[33 + d] = mx;
    }
}

// =================== out v5: 8 rows/block (halved W_R traffic) ===============
__global__ __launch_bounds__(256)
void out_kernel(const float* __restrict__ W_R, float* __restrict__ out) {
    __shared__ __align__(16) float smt[AGG][8];   // multi^T for 8 rows
    __shared__ float s_part[8][128];

    const int tid  = threadIdx.x;
    const int row0 = blockIdx.x * 8;

    for (int i = tid; i < 8 * AGG; i += 256) {
        int r = i / AGG, k = i - r * AGG;
        smt[k][r] = g_multi[(size_t)(row0 + r) * AGG + k];
    }
    __syncthreads();

    const int o  = tid & 127;
    const int kh = tid >> 7;
    const int kb = kh * 130;
    const float2* wr = (const float2*)(W_R + o * AGG + kb);  // 8B-aligned
    float a[8] = {0.f, 0.f, 0.f, 0.f, 0.f, 0.f, 0.f, 0.f};
    #pragma unroll 5
    for (int j = 0; j < 65; j++) {
        float2 w  = wr[j];
        const float* m0 = smt[kb + 2 * j];
        const float* m1 = smt[kb + 2 * j + 1];
        #pragma unroll
        for (int r = 0; r < 8; r++)
            a[r] += m0[r] * w.x + m1[r] * w.y;
    }
    if (kh == 0) {
        #pragma unroll
        for (int r = 0; r < 8; r++) s_part[r][o] = a[r];
    }
    __syncthreads();
    if (kh == 1) {
        #pragma unroll
        for (int r = 0; r < 8; r++)
            out[(size_t)(row0 + r) * 128 + o] = s_part[r][o] + a[r];
    }
}

// =================== launch ===================
extern "C" void kernel_launch(void* const* d_in, const int* in_sizes, int n_in,
                              void* d_out, int out_size) {
    (void)in_sizes; (void)n_in; (void)out_size;
    const float* h_x = (const float*)d_in[0];
    const float* h_e = (const float*)d_in[1];
    const float* h_m = (const float*)d_in[2];
    const float* W_Q = (const float*)d_in[3];
    const float* W_K = (const float*)d_in[4];
    const float* W_V = (const float*)d_in[5];
    const float* W_R = (const float*)d_in[6];
    float* out = (float*)d_out;

    cudaFuncSetAttribute(main_kernel,
                         cudaFuncAttributeMaxDynamicSharedMemorySize, DYN_SMEM);

    prep_kernel<<<260, 256>>>(W_Q, W_K, W_V);
    qk_kernel<<<128, 256>>>(h_x);
    main_kernel<<<ROWS, 256, DYN_SMEM>>>(h_e, h_m);
    out_kernel<<<128, 256>>>(W_R, out);
}

// round 11
// speedup vs baseline: 1.4036x; 1.1768x over previous
#include <cuda_runtime.h>
#include <cuda_bf16.h>
#include <cstdint>

typedef unsigned int       u32;
typedef unsigned long long u64;

#define ROWS 1024
#define AGG  260

__device__ float g_Mfold[256 * 256];   // [x][h*64+e], 1/sqrt(D) folded
__device__ float g_qk[ROWS * 256];
__device__ u32   g_WVh[4096];          // W_V hi bf16x2, [c*32 + e/2]
__device__ u32   g_WVl[4096];          // W_V lo bf16x2 (scores not needed; kept for layout)
__device__ float g_multi[ROWS * AGG];

// ---------------- f32x2 helpers ----------------
__device__ __forceinline__ u64 pack2(float a, float b) {
    u64 r; asm("mov.b64 %0, {%1, %2};" : "=l"(r) : "f"(a), "f"(b)); return r;
}
__device__ __forceinline__ void unpack2(u64 v, float& a, float& b) {
    asm("mov.b64 {%0, %1}, %2;" : "=f"(a), "=f"(b) : "l"(v));
}
__device__ __forceinline__ u64 fma2(u64 a, u64 b, u64 c) {
    u64 d; asm("fma.rn.f32x2 %0, %1, %2, %3;" : "=l"(d) : "l"(a), "l"(b), "l"(c));
    return d;
}

// ---------------- warp mma: m16n8k16 bf16, D/C f32, accumulate in-place ----
__device__ __forceinline__ void mma16816(float* d, const u32* a, const u32* b) {
    asm volatile(
        "mma.sync.aligned.m16n8k16.row.col.f32.bf16.bf16.f32 "
        "{%0,%1,%2,%3}, {%4,%5,%6,%7}, {%8,%9}, {%0,%1,%2,%3};"
        : "+f"(d[0]), "+f"(d[1]), "+f"(d[2]), "+f"(d[3])
        : "r"(a[0]), "r"(a[1]), "r"(a[2]), "r"(a[3]), "r"(b[0]), "r"(b[1]));
}

// rotation swizzle: row m (32 u32), logical col c -> conflict-free banks
#define BP(m, c) ((m) * 32 + (((c) + ((m) << 2)) & 31))

// =================== prep: Mfold + W_V bf16 hi split ===========
__global__ __launch_bounds__(256)
void prep_kernel(const float* __restrict__ WQ, const float* __restrict__ WK,
                 const float* __restrict__ WV) {
    const int b = blockIdx.x, tid = threadIdx.x;
    if (b < 256) {
        __shared__ float wq[128];
        if (tid < 128) wq[tid] = WQ[tid * 256 + b];
        __syncthreads();
        const int h = tid >> 6, e = tid & 63;
        float acc = 0.f;
        #pragma unroll 8
        for (int d = 0; d < 32; d++)
            acc += wq[h * 32 + d] * WK[(h * 32 + d) * 64 + e];
        g_Mfold[b * 256 + tid] = acc * 0.1767766952966369f;  // 1/sqrt(32)
    } else {
        #pragma unroll
        for (int r = 0; r < 4; r++) {
            int idx = (b - 256) * 1024 + r * 256 + tid;  // < 4096
            int c = idx >> 5, e0 = (idx & 31) * 2;
            float x0 = WV[c * 64 + e0], x1 = WV[c * 64 + e0 + 1];
            __nv_bfloat16 h0 = __float2bfloat16(x0), h1 = __float2bfloat16(x1);
            __nv_bfloat162 hp = __halves2bfloat162(h0, h1);
            g_WVh[idx] = *(u32*)&hp;
        }
    }
}

// =================== qk = h_x @ Mfold (unroll 16 for MLP) ===================
__global__ __launch_bounds__(256)
void qk_kernel(const float* __restrict__ hx) {
    __shared__ float sx[8][256];
    const int tid = threadIdx.x, r0 = blockIdx.x * 8;
    for (int i = tid; i < 2048; i += 256) sx[i >> 8][i & 255] = hx[r0 * 256 + i];
    __syncthreads();
    float a[8] = {0.f, 0.f, 0.f, 0.f, 0.f, 0.f, 0.f, 0.f};
    #pragma unroll 16
    for (int x = 0; x < 256; x++) {
        float mf = g_Mfold[x * 256 + tid];
        #pragma unroll
        for (int k = 0; k < 8; k++) a[k] += sx[k][x] * mf;
    }
    #pragma unroll
    for (int k = 0; k < 8; k++) g_qk[(r0 + k) * 256 + tid] = a[k];
}

// =================== main: 1-term Ah*Bh, 3 CTAs/SM ============
#define DYN_SMEM (2 * 32768)

__global__ __launch_bounds__(256, 3)
void main_kernel(const float* __restrict__ h_e, const float* __restrict__ h_m) {
    extern __shared__ u32 dynu[];
    __shared__ __align__(16) float s_qk[256];
    __shared__ float s_attn[1024];
    __shared__ float s_asum[4];
    __shared__ float s_ps[2][128];
    __shared__ float s_pm[2][128];

    u32* s_bhi = dynu;           // [256 m][32 u32], rotation-swizzled
    u32* s_blo = dynu + 8192;    // lo half: fp32 score reconstruction only

    const int bn   = blockIdx.x;
    const int tid  = threadIdx.x;
    const int wid  = tid >> 5;
    const int lane = tid & 31;
    const int gid  = lane >> 2;
    const int tid4 = lane & 3;
    const int cg   = wid & 3;    // c-group = head
    const int mh   = wid >> 2;   // m-half
    const int cbase = cg * 32;

    if (tid < 4) s_asum[tid] = 0.f;

    // ---- convert h_e -> bf16 hi/lo swizzled smem (STS.64) ----
    const float4* src = (const float4*)(h_e + (size_t)bn * 16384);
    #pragma unroll
    for (int it = 0; it < 16; it++) {
        int flat = it * 256 + tid;
        int m = flat >> 4, c0 = (flat & 15) * 2;
        float4 v = src[flat];
        __nv_bfloat16 b0 = __float2bfloat16(v.x), b1 = __float2bfloat16(v.y);
        __nv_bfloat16 b2 = __float2bfloat16(v.z), b3 = __float2bfloat16(v.w);
        __nv_bfloat16 l0 = __float2bfloat16(v.x - __bfloat162float(b0));
        __nv_bfloat16 l1 = __float2bfloat16(v.y - __bfloat162float(b1));
        __nv_bfloat16 l2 = __float2bfloat16(v.z - __bfloat162float(b2));
        __nv_bfloat16 l3 = __float2bfloat16(v.w - __bfloat162float(b3));
        __nv_bfloat162 h01 = __halves2bfloat162(b0, b1);
        __nv_bfloat162 h23 = __halves2bfloat162(b2, b3);
        __nv_bfloat162 q01 = __halves2bfloat162(l0, l1);
        __nv_bfloat162 q23 = __halves2bfloat162(l2, l3);
        u32 base = BP(m, c0);   // even, 8B-aligned; BP(m,c0+1)=base+1
        *(u64*)(s_bhi + base) = (u64)(*(u32*)&h01) | ((u64)(*(u32*)&h23) << 32);
        *(u64*)(s_blo + base) = (u64)(*(u32*)&q01) | ((u64)(*(u32*)&q23) << 32);
    }
    s_qk[tid] = g_qk[bn * 256 + tid];
    const float maskv = h_m[bn];

    // ---- A fragments (W_V hi) -> registers, 2 c-tiles per warp ----
    u32 Ah[2][16];
    #pragma unroll
    for (int j = 0; j < 2; j++) {
        int r0 = cbase + j * 16 + gid;
        #pragma unroll
        for (int ks = 0; ks < 4; ks++) {
            int b0 = r0 * 32 + ks * 8 + tid4;
            int b1 = (r0 + 8) * 32 + ks * 8 + tid4;
            Ah[j][ks * 4 + 0] = g_WVh[b0];
            Ah[j][ks * 4 + 1] = g_WVh[b1];
            Ah[j][ks * 4 + 2] = g_WVh[b0 + 4];
            Ah[j][ks * 4 + 3] = g_WVh[b1 + 4];
        }
    }
    __syncthreads();

    // ---- scores + softmax over heads (thread = m); full fp32 via hi+lo ----
    {
        const int m = tid;
        u64 acc0 = 0ull, acc1 = 0ull, acc2 = 0ull, acc3 = 0ull;
        const u64* qp = (const u64*)s_qk;
        #pragma unroll 8
        for (int j = 0; j < 32; j++) {
            int ep = (j + m) & 31;                   // bank-spread order
            int pi = BP(m, ep);
            u32 h2 = s_bhi[pi], l2 = s_blo[pi];
            float2 fh = __bfloat1622float2(*(__nv_bfloat162*)&h2);
            float2 fl = __bfloat1622float2(*(__nv_bfloat162*)&l2);
            u64 he = pack2(fh.x + fl.x, fh.y + fl.y);
            acc0 = fma2(he, qp[ep],      acc0);
            acc1 = fma2(he, qp[32 + ep], acc1);
            acc2 = fma2(he, qp[64 + ep], acc2);
            acc3 = fma2(he, qp[96 + ep], acc3);
        }
        float x, y, s0, s1, s2, s3;
        unpack2(acc0, x, y); s0 = x + y;
        unpack2(acc1, x, y); s1 = x + y;
        unpack2(acc2, x, y); s2 = x + y;
        unpack2(acc3, x, y); s3 = x + y;
        if (maskv == 0.f) {
            const float ninf = __int_as_float(0xff800000);
            s0 = s1 = s2 = s3 = ninf;
        }
        float mx = fmaxf(fmaxf(s0, s1), fmaxf(s2, s3));
        float e0 = __expf(s0 - mx), e1 = __expf(s1 - mx);
        float e2 = __expf(s2 - mx), e3 = __expf(s3 - mx);
        float r  = 1.f / (e0 + e1 + e2 + e3);
        float a0 = e0 * r, a1 = e1 * r, a2 = e2 * r, a3 = e3 * r;
        s_attn[m]       = a0;
        s_attn[256 + m] = a1;
        s_attn[512 + m] = a2;
        s_attn[768 + m] = a3;
        float t0 = a0, t1 = a1, t2 = a2, t3 = a3;
        #pragma unroll
        for (int off = 16; off; off >>= 1) {
            t0 += __shfl_xor_sync(0xffffffffu, t0, off);
            t1 += __shfl_xor_sync(0xffffffffu, t1, off);
            t2 += __shfl_xor_sync(0xffffffffu, t2, off);
            t3 += __shfl_xor_sync(0xffffffffu, t3, off);
        }
        if (lane == 0) {
            atomicAdd(&s_asum[0], t0);
            atomicAdd(&s_asum[1], t1);
            atomicAdd(&s_asum[2], t2);
            atomicAdd(&s_asum[3], t3);
        }
    }
    __syncthreads();

    // ---- mainloop: 16 m-tiles x 2 c-tiles, 1-term Ah*Bh ----
    const float ninf = __int_as_float(0xff800000);
    float sum0 = 0.f, sum1 = 0.f, sum2 = 0.f, sum3 = 0.f;
    float mx0 = ninf, mx1 = ninf, mx2 = ninf, mx3 = ninf;
    const float* ap = s_attn + cg * 256;

    for (int t = 0; t < 16; t++) {
        const int mbase = mh * 128 + t * 8;
        const int mrow  = mbase + gid;
        u32 Bh[8];
        #pragma unroll
        for (int ks = 0; ks < 4; ks++) {
            int c0 = ks * 8 + tid4;
            Bh[ks * 2]     = s_bhi[BP(mrow, c0)];
            Bh[ks * 2 + 1] = s_bhi[BP(mrow, c0 + 4)];
        }
        float2 at = *(const float2*)(ap + mbase + 2 * tid4);
        #pragma unroll
        for (int j = 0; j < 2; j++) {
            float d[4] = {0.f, 0.f, 0.f, 0.f};
            #pragma unroll
            for (int ks = 0; ks < 4; ks++)
                mma16816(d, &Ah[j][ks * 4], &Bh[ks * 2]);
            float w0 = at.x * d[0], w1 = at.y * d[1];
            float w2 = at.x * d[2], w3 = at.y * d[3];
            if (j == 0) {
                sum0 += w0 + w1; sum1 += w2 + w3;
                mx0 = fmaxf(mx0, fmaxf(w0, w1));
                mx1 = fmaxf(mx1, fmaxf(w2, w3));
            } else {
                sum2 += w0 + w1; sum3 += w2 + w3;
                mx2 = fmaxf(mx2, fmaxf(w0, w1));
                mx3 = fmaxf(mx3, fmaxf(w2, w3));
            }
        }
    }

    // reduce across quad (tid4)
    #pragma unroll
    for (int off = 1; off <= 2; off <<= 1) {
        sum0 += __shfl_xor_sync(0xffffffffu, sum0, off);
        sum1 += __shfl_xor_sync(0xffffffffu, sum1, off);
        sum2 += __shfl_xor_sync(0xffffffffu, sum2, off);
        sum3 += __shfl_xor_sync(0xffffffffu, sum3, off);
        mx0 = fmaxf(mx0, __shfl_xor_sync(0xffffffffu, mx0, off));
        mx1 = fmaxf(mx1, __shfl_xor_sync(0xffffffffu, mx1, off));
        mx2 = fmaxf(mx2, __shfl_xor_sync(0xffffffffu, mx2, off));
        mx3 = fmaxf(mx3, __shfl_xor_sync(0xffffffffu, mx3, off));
    }
    if (tid4 == 0) {
        s_ps[mh][cbase + gid]      = sum0;  s_pm[mh][cbase + gid]      = mx0;
        s_ps[mh][cbase + gid + 8]  = sum1;  s_pm[mh][cbase + gid + 8]  = mx1;
        s_ps[mh][cbase + gid + 16] = sum2;  s_pm[mh][cbase + gid + 16] = mx2;
        s_ps[mh][cbase + gid + 24] = sum3;  s_pm[mh][cbase + gid + 24] = mx3;
    }
    __syncthreads();

    if (tid < 128) {
        const int c = tid, h = c >> 5, d = c & 31;
        float s  = s_ps[0][c] + s_ps[1][c];
        float mx = fmaxf(s_pm[0][c], s_pm[1][c]);
        float asum = s_asum[h] + 1e-8f;
        float* mrow = g_multi + (size_t)bn * AGG + h * 65;
        mrow[d]      = s / asum;
        if (d == 0) mrow[32] = asum;
        mrow[33 + d] = mx;
    }
}

// =================== out v3 (measured best: 15.1us) ===================
__global__ __launch_bounds__(256)
void out_kernel(const float* __restrict__ W_R, float* __restrict__ out) {
    __shared__ __align__(16) float smt[AGG][4];   // multi^T for this block's 4 rows
    __shared__ float s_part[4][128];

    const int tid  = threadIdx.x;
    const int row0 = blockIdx.x * 4;

    for (int i = tid; i < 4 * AGG; i += 256) {
        int r = i / AGG, k = i - r * AGG;
        smt[k][r] = g_multi[(size_t)(row0 + r) * AGG + k];
    }
    __syncthreads();

    const int o  = tid & 127;
    const int kh = tid >> 7;
    const int kb = kh * 130;
    const float2* wr = (const float2*)(W_R + o * AGG + kb);  // 8B-aligned
    float a0 = 0.f, a1 = 0.f, a2 = 0.f, a3 = 0.f;
    #pragma unroll 5
    for (int j = 0; j < 65; j++) {
        float2 w  = wr[j];
        float4 m0 = *(const float4*)smt[kb + 2 * j];
        float4 m1 = *(const float4*)smt[kb + 2 * j + 1];
        a0 += m0.x * w.x + m1.x * w.y;
        a1 += m0.y * w.x + m1.y * w.y;
        a2 += m0.z * w.x + m1.z * w.y;
        a3 += m0.w * w.x + m1.w * w.y;
    }
    if (kh == 0) {
        s_part[0][o] = a0; s_part[1][o] = a1;
        s_part[2][o] = a2; s_part[3][o] = a3;
    }
    __syncthreads();
    if (kh == 1) {
        out[(size_t)(row0 + 0) * 128 + o] = s_part[0][o] + a0;
        out[(size_t)(row0 + 1) * 128 + o] = s_part[1][o] + a1;
        out[(size_t)(row0 + 2) * 128 + o] = s_part[2][o] + a2;
        out[(size_t)(row0 + 3) * 128 + o] = s_part[3][o] + a3;
    }
}

// =================== launch ===================
extern "C" void kernel_launch(void* const* d_in, const int* in_sizes, int n_in,
                              void* d_out, int out_size) {
    (void)in_sizes; (void)n_in; (void)out_size;
    const float* h_x = (const float*)d_in[0];
    const float* h_e = (const float*)d_in[1];
    const float* h_m = (const float*)d_in[2];
    const float* W_Q = (const float*)d_in[3];
    const float* W_K = (const float*)d_in[4];
    const float* W_V = (const float*)d_in[5];
    const float* W_R = (const float*)d_in[6];
    float* out = (float*)d_out;

    cudaFuncSetAttribute(main_kernel,
                         cudaFuncAttributeMaxDynamicSharedMemorySize, DYN_SMEM);

    prep_kernel<<<260, 256>>>(W_Q, W_K, W_V);
    qk_kernel<<<128, 256>>>(h_x);
    main_kernel<<<ROWS, 256, DYN_SMEM>>>(h_e, h_m);
    out_kernel<<<256, 256>>>(W_R, out);
}

// round 12
// speedup vs baseline: 1.5274x; 1.0882x over previous
#include <cuda_runtime.h>
#include <cuda_bf16.h>
#include <cstdint>

typedef unsigned int       u32;
typedef unsigned long long u64;

#define ROWS 1024
#define AGG  260

__device__ float g_Mfold[256 * 256];   // [x][h*64+e], 1/sqrt(D) folded
__device__ float g_qk[ROWS * 256];
__device__ u32   g_WVh[4096];          // W_V hi bf16x2, [c*32 + e/2]
__device__ float g_multi[ROWS * AGG];

// ---------------- warp mma: m16n8k16 bf16, D/C f32, accumulate in-place ----
__device__ __forceinline__ void mma16816(float* d, const u32* a, const u32* b) {
    asm volatile(
        "mma.sync.aligned.m16n8k16.row.col.f32.bf16.bf16.f32 "
        "{%0,%1,%2,%3}, {%4,%5,%6,%7}, {%8,%9}, {%0,%1,%2,%3};"
        : "+f"(d[0]), "+f"(d[1]), "+f"(d[2]), "+f"(d[3])
        : "r"(a[0]), "r"(a[1]), "r"(a[2]), "r"(a[3]), "r"(b[0]), "r"(b[1]));
}

// rotation swizzle: row m (32 u32), logical col c -> conflict-free banks
#define BP(m, c) ((m) * 32 + (((c) + ((m) << 2)) & 31))

// =================== prep: Mfold + W_V bf16 hi ===========
__global__ __launch_bounds__(256)
void prep_kernel(const float* __restrict__ WQ, const float* __restrict__ WK,
                 const float* __restrict__ WV) {
    const int b = blockIdx.x, tid = threadIdx.x;
    if (b < 256) {
        __shared__ float wq[128];
        if (tid < 128) wq[tid] = WQ[tid * 256 + b];
        __syncthreads();
        const int h = tid >> 6, e = tid & 63;
        float acc = 0.f;
        #pragma unroll 8
        for (int d = 0; d < 32; d++)
            acc += wq[h * 32 + d] * WK[(h * 32 + d) * 64 + e];
        g_Mfold[b * 256 + tid] = acc * 0.1767766952966369f;  // 1/sqrt(32)
    } else {
        #pragma unroll
        for (int r = 0; r < 4; r++) {
            int idx = (b - 256) * 1024 + r * 256 + tid;  // < 4096
            int c = idx >> 5, e0 = (idx & 31) * 2;
            float x0 = WV[c * 64 + e0], x1 = WV[c * 64 + e0 + 1];
            __nv_bfloat16 h0 = __float2bfloat16(x0), h1 = __float2bfloat16(x1);
            __nv_bfloat162 hp = __halves2bfloat162(h0, h1);
            g_WVh[idx] = *(u32*)&hp;
        }
    }
}

// =================== qk = h_x @ Mfold (unroll 16) ===================
__global__ __launch_bounds__(256)
void qk_kernel(const float* __restrict__ hx) {
    __shared__ float sx[8][256];
    const int tid = threadIdx.x, r0 = blockIdx.x * 8;
    for (int i = tid; i < 2048; i += 256) sx[i >> 8][i & 255] = hx[r0 * 256 + i];
    __syncthreads();
    float a[8] = {0.f, 0.f, 0.f, 0.f, 0.f, 0.f, 0.f, 0.f};
    #pragma unroll 16
    for (int x = 0; x < 256; x++) {
        float mf = g_Mfold[x * 256 + tid];
        #pragma unroll
        for (int k = 0; k < 8; k++) a[k] += sx[k][x] * mf;
    }
    #pragma unroll
    for (int k = 0; k < 8; k++) g_qk[(r0 + k) * 256 + tid] = a[k];
}

// =================== main: fused fp32 scores in convert, 4 CTAs/SM ===========
#define DYN_SMEM 32768

__global__ __launch_bounds__(256, 4)
void main_kernel(const float* __restrict__ h_e, const float* __restrict__ h_m) {
    extern __shared__ u32 dynu[];
    __shared__ __align__(16) float s_qk[256];
    __shared__ float s_attn[1024];
    __shared__ float s_asum[4];
    __shared__ float s_ps[2][128];
    __shared__ float s_pm[2][128];

    u32* s_bhi = dynu;           // [256 m][32 u32], rotation-swizzled

    const int bn   = blockIdx.x;
    const int tid  = threadIdx.x;
    const int wid  = tid >> 5;
    const int lane = tid & 31;
    const int gid  = lane >> 2;
    const int tid4 = lane & 3;
    const int cg   = wid & 3;    // c-group = head
    const int mh   = wid >> 2;   // m-half
    const int cbase = cg * 32;

    if (tid < 4) s_asum[tid] = 0.f;
    s_qk[tid] = g_qk[bn * 256 + tid];
    const float maskv = h_m[bn];
    __syncthreads();

    // qk weights for this thread's constant e-chunk, all 4 heads
    const int e0 = (tid & 15) * 4;
    float qkr[16];
    #pragma unroll
    for (int h = 0; h < 4; h++) {
        float4 q = *(const float4*)(s_qk + h * 64 + e0);
        qkr[h * 4 + 0] = q.x; qkr[h * 4 + 1] = q.y;
        qkr[h * 4 + 2] = q.z; qkr[h * 4 + 3] = q.w;
    }
    const int c0 = (tid & 15) * 2;   // constant bf16x2 col pair

    // ---- convert h_e -> bf16 hi smem + fused fp32 partial scores ----
    const float4* src = (const float4*)(h_e + (size_t)bn * 16384);
    #pragma unroll
    for (int it = 0; it < 16; it++) {
        int flat = it * 256 + tid;
        int m = flat >> 4;
        float4 v = src[flat];
        __nv_bfloat16 b0 = __float2bfloat16(v.x), b1 = __float2bfloat16(v.y);
        __nv_bfloat16 b2 = __float2bfloat16(v.z), b3 = __float2bfloat16(v.w);
        __nv_bfloat162 h01 = __halves2bfloat162(b0, b1);
        __nv_bfloat162 h23 = __halves2bfloat162(b2, b3);
        u32 base = BP(m, c0);   // even, 8B-aligned; BP(m,c0+1)=base+1
        *(u64*)(s_bhi + base) = (u64)(*(u32*)&h01) | ((u64)(*(u32*)&h23) << 32);

        // exact fp32 partial scores (pre-truncation values)
        float p0 = v.x * qkr[0]  + v.y * qkr[1]  + v.z * qkr[2]  + v.w * qkr[3];
        float p1 = v.x * qkr[4]  + v.y * qkr[5]  + v.z * qkr[6]  + v.w * qkr[7];
        float p2 = v.x * qkr[8]  + v.y * qkr[9]  + v.z * qkr[10] + v.w * qkr[11];
        float p3 = v.x * qkr[12] + v.y * qkr[13] + v.z * qkr[14] + v.w * qkr[15];
        #pragma unroll
        for (int off = 1; off < 16; off <<= 1) {
            p0 += __shfl_xor_sync(0xffffffffu, p0, off);
            p1 += __shfl_xor_sync(0xffffffffu, p1, off);
            p2 += __shfl_xor_sync(0xffffffffu, p2, off);
            p3 += __shfl_xor_sync(0xffffffffu, p3, off);
        }
        if ((tid & 15) == 0) {
            s_attn[m]       = p0;
            s_attn[256 + m] = p1;
            s_attn[512 + m] = p2;
            s_attn[768 + m] = p3;
        }
    }

    // ---- A fragments (W_V hi) -> registers, 2 c-tiles per warp ----
    u32 Ah[2][16];
    #pragma unroll
    for (int j = 0; j < 2; j++) {
        int r0 = cbase + j * 16 + gid;
        #pragma unroll
        for (int ks = 0; ks < 4; ks++) {
            int b0 = r0 * 32 + ks * 8 + tid4;
            int b1 = (r0 + 8) * 32 + ks * 8 + tid4;
            Ah[j][ks * 4 + 0] = g_WVh[b0];
            Ah[j][ks * 4 + 1] = g_WVh[b1];
            Ah[j][ks * 4 + 2] = g_WVh[b0 + 4];
            Ah[j][ks * 4 + 3] = g_WVh[b1 + 4];
        }
    }
    __syncthreads();

    // ---- softmax over heads (thread = m) ----
    {
        const int m = tid;
        float s0 = s_attn[m],       s1 = s_attn[256 + m];
        float s2 = s_attn[512 + m], s3 = s_attn[768 + m];
        if (maskv == 0.f) {
            const float ninf = __int_as_float(0xff800000);
            s0 = s1 = s2 = s3 = ninf;
        }
        float mx = fmaxf(fmaxf(s0, s1), fmaxf(s2, s3));
        float e0f = __expf(s0 - mx), e1f = __expf(s1 - mx);
        float e2f = __expf(s2 - mx), e3f = __expf(s3 - mx);
        float r  = 1.f / (e0f + e1f + e2f + e3f);
        float a0 = e0f * r, a1 = e1f * r, a2 = e2f * r, a3 = e3f * r;
        s_attn[m]       = a0;
        s_attn[256 + m] = a1;
        s_attn[512 + m] = a2;
        s_attn[768 + m] = a3;
        float t0 = a0, t1 = a1, t2 = a2, t3 = a3;
        #pragma unroll
        for (int off = 16; off; off >>= 1) {
            t0 += __shfl_xor_sync(0xffffffffu, t0, off);
            t1 += __shfl_xor_sync(0xffffffffu, t1, off);
            t2 += __shfl_xor_sync(0xffffffffu, t2, off);
            t3 += __shfl_xor_sync(0xffffffffu, t3, off);
        }
        if (lane == 0) {
            atomicAdd(&s_asum[0], t0);
            atomicAdd(&s_asum[1], t1);
            atomicAdd(&s_asum[2], t2);
            atomicAdd(&s_asum[3], t3);
        }
    }
    __syncthreads();

    // ---- mainloop: 16 m-tiles x 2 c-tiles, 1-term Ah*Bh ----
    const float ninf = __int_as_float(0xff800000);
    float sum0 = 0.f, sum1 = 0.f, sum2 = 0.f, sum3 = 0.f;
    float mx0 = ninf, mx1 = ninf, mx2 = ninf, mx3 = ninf;
    const float* ap = s_attn + cg * 256;

    for (int t = 0; t < 16; t++) {
        const int mbase = mh * 128 + t * 8;
        const int mrow  = mbase + gid;
        u32 Bh[8];
        #pragma unroll
        for (int ks = 0; ks < 4; ks++) {
            int cc = ks * 8 + tid4;
            Bh[ks * 2]     = s_bhi[BP(mrow, cc)];
            Bh[ks * 2 + 1] = s_bhi[BP(mrow, cc + 4)];
        }
        float2 at = *(const float2*)(ap + mbase + 2 * tid4);
        #pragma unroll
        for (int j = 0; j < 2; j++) {
            float d[4] = {0.f, 0.f, 0.f, 0.f};
            #pragma unroll
            for (int ks = 0; ks < 4; ks++)
                mma16816(d, &Ah[j][ks * 4], &Bh[ks * 2]);
            float w0 = at.x * d[0], w1 = at.y * d[1];
            float w2 = at.x * d[2], w3 = at.y * d[3];
            if (j == 0) {
                sum0 += w0 + w1; sum1 += w2 + w3;
                mx0 = fmaxf(mx0, fmaxf(w0, w1));
                mx1 = fmaxf(mx1, fmaxf(w2, w3));
            } else {
                sum2 += w0 + w1; sum3 += w2 + w3;
                mx2 = fmaxf(mx2, fmaxf(w0, w1));
                mx3 = fmaxf(mx3, fmaxf(w2, w3));
            }
        }
    }

    // reduce across quad (tid4)
    #pragma unroll
    for (int off = 1; off <= 2; off <<= 1) {
        sum0 += __shfl_xor_sync(0xffffffffu, sum0, off);
        sum1 += __shfl_xor_sync(0xffffffffu, sum1, off);
        sum2 += __shfl_xor_sync(0xffffffffu, sum2, off);
        sum3 += __shfl_xor_sync(0xffffffffu, sum3, off);
        mx0 = fmaxf(mx0, __shfl_xor_sync(0xffffffffu, mx0, off));
        mx1 = fmaxf(mx1, __shfl_xor_sync(0xffffffffu, mx1, off));
        mx2 = fmaxf(mx2, __shfl_xor_sync(0xffffffffu, mx2, off));
        mx3 = fmaxf(mx3, __shfl_xor_sync(0xffffffffu, mx3, off));
    }
    if (tid4 == 0) {
        s_ps[mh][cbase + gid]      = sum0;  s_pm[mh][cbase + gid]      = mx0;
        s_ps[mh][cbase + gid + 8]  = sum1;  s_pm[mh][cbase + gid + 8]  = mx1;
        s_ps[mh][cbase + gid + 16] = sum2;  s_pm[mh][cbase + gid + 16] = mx2;
        s_ps[mh][cbase + gid + 24] = sum3;  s_pm[mh][cbase + gid + 24] = mx3;
    }
    __syncthreads();

    if (tid < 128) {
        const int c = tid, h = c >> 5, d = c & 31;
        float s  = s_ps[0][c] + s_ps[1][c];
        float mx = fmaxf(s_pm[0][c], s_pm[1][c]);
        float asum = s_asum[h] + 1e-8f;
        float* mrow = g_multi + (size_t)bn * AGG + h * 65;
        mrow[d]      = s / asum;
        if (d == 0) mrow[32] = asum;
        mrow[33 + d] = mx;
    }
}

// =================== out v6: v3 + float4 W_R stream (k split 128/132) ========
__global__ __launch_bounds__(256)
void out_kernel(const float* __restrict__ W_R, float* __restrict__ out) {
    __shared__ __align__(16) float smt[AGG][4];   // multi^T for this block's 4 rows
    __shared__ float s_part[4][128];

    const int tid  = threadIdx.x;
    const int row0 = blockIdx.x * 4;

    for (int i = tid; i < 4 * AGG; i += 256) {
        int r = i / AGG, k = i - r * AGG;
        smt[k][r] = g_multi[(size_t)(row0 + r) * AGG + k];
    }
    __syncthreads();

    const int o  = tid & 127;
    const int kh = tid >> 7;
    const int kb = kh * 128;                       // 0 or 128; both 16B-aligned
    const float4* wr4 = (const float4*)(W_R + o * AGG + kb);
    float a0 = 0.f, a1 = 0.f, a2 = 0.f, a3 = 0.f;
    #pragma unroll 8
    for (int j = 0; j < 32; j++) {
        float4 w  = wr4[j];
        int k = kb + 4 * j;
        float4 m0 = *(const float4*)smt[k];
        float4 m1 = *(const float4*)smt[k + 1];
        float4 m2 = *(const float4*)smt[k + 2];
        float4 m3 = *(const float4*)smt[k + 3];
        a0 += m0.x * w.x + m1.x * w.y + m2.x * w.z + m3.x * w.w;
        a1 += m0.y * w.x + m1.y * w.y + m2.y * w.z + m3.y * w.w;
        a2 += m0.z * w.x + m1.z * w.y + m2.z * w.z + m3.z * w.w;
        a3 += m0.w * w.x + m1.w * w.y + m2.w * w.z + m3.w * w.w;
    }
    if (kh) {   // extra float4 covering k = 256..259 (132-float half)
        float4 w  = wr4[32];
        float4 m0 = *(const float4*)smt[256];
        float4 m1 = *(const float4*)smt[257];
        float4 m2 = *(const float4*)smt[258];
        float4 m3 = *(const float4*)smt[259];
        a0 += m0.x * w.x + m1.x * w.y + m2.x * w.z + m3.x * w.w;
        a1 += m0.y * w.x + m1.y * w.y + m2.y * w.z + m3.y * w.w;
        a2 += m0.z * w.x + m1.z * w.y + m2.z * w.z + m3.z * w.w;
        a3 += m0.w * w.x + m1.w * w.y + m2.w * w.z + m3.w * w.w;
    }
    if (kh == 0) {
        s_part[0][o] = a0; s_part[1][o] = a1;
        s_part[2][o] = a2; s_part[3][o] = a3;
    }
    __syncthreads();
    if (kh == 1) {
        out[(size_t)(row0 + 0) * 128 + o] = s_part[0][o] + a0;
        out[(size_t)(row0 + 1) * 128 + o] = s_part[1][o] + a1;
        out[(size_t)(row0 + 2) * 128 + o] = s_part[2][o] + a2;
        out[(size_t)(row0 + 3) * 128 + o] = s_part[3][o] + a3;
    }
}

// =================== launch ===================
extern "C" void kernel_launch(void* const* d_in, const int* in_sizes, int n_in,
                              void* d_out, int out_size) {
    (void)in_sizes; (void)n_in; (void)out_size;
    const float* h_x = (const float*)d_in[0];
    const float* h_e = (const float*)d_in[1];
    const float* h_m = (const float*)d_in[2];
    const float* W_Q = (const float*)d_in[3];
    const float* W_K = (const float*)d_in[4];
    const float* W_V = (const float*)d_in[5];
    const float* W_R = (const float*)d_in[6];
    float* out = (float*)d_out;

    cudaFuncSetAttribute(main_kernel,
                         cudaFuncAttributeMaxDynamicSharedMemorySize, DYN_SMEM);

    prep_kernel<<<260, 256>>>(W_Q, W_K, W_V);
    qk_kernel<<<128, 256>>>(h_x);
    main_kernel<<<ROWS, 256, DYN_SMEM>>>(h_e, h_m);
    out_kernel<<<256, 256>>>(W_R, out);
}

// round 13
// speedup vs baseline: 1.5630x; 1.0233x over previous
#include <cuda_runtime.h>
#include <cuda_bf16.h>
#include <cstdint>

typedef unsigned int       u32;
typedef unsigned long long u64;

#define ROWS 1024
#define AGG  260

__device__ float g_Mfold[256 * 256];   // [x][h*64+e], 1/sqrt(D) folded
__device__ float g_qk[ROWS * 256];
__device__ u32   g_WVh[4096];          // W_V hi bf16x2, [c*32 + e/2]
__device__ float g_multi[ROWS * AGG];

// ---------------- warp mma: m16n8k16 bf16, D/C f32, accumulate in-place ----
__device__ __forceinline__ void mma16816(float* d, const u32* a, const u32* b) {
    asm volatile(
        "mma.sync.aligned.m16n8k16.row.col.f32.bf16.bf16.f32 "
        "{%0,%1,%2,%3}, {%4,%5,%6,%7}, {%8,%9}, {%0,%1,%2,%3};"
        : "+f"(d[0]), "+f"(d[1]), "+f"(d[2]), "+f"(d[3])
        : "r"(a[0]), "r"(a[1]), "r"(a[2]), "r"(a[3]), "r"(b[0]), "r"(b[1]));
}

// rotation swizzle: row m (32 u32), logical col c -> conflict-free banks
#define BP(m, c) ((m) * 32 + (((c) + ((m) << 2)) & 31))

// =================== prep: Mfold + W_V bf16 hi ===========
__global__ __launch_bounds__(256)
void prep_kernel(const float* __restrict__ WQ, const float* __restrict__ WK,
                 const float* __restrict__ WV) {
    const int b = blockIdx.x, tid = threadIdx.x;
    if (b < 256) {
        __shared__ float wq[128];
        if (tid < 128) wq[tid] = WQ[tid * 256 + b];
        __syncthreads();
        const int h = tid >> 6, e = tid & 63;
        float acc = 0.f;
        #pragma unroll 8
        for (int d = 0; d < 32; d++)
            acc += wq[h * 32 + d] * WK[(h * 32 + d) * 64 + e];
        g_Mfold[b * 256 + tid] = acc * 0.1767766952966369f;  // 1/sqrt(32)
    } else {
        #pragma unroll
        for (int r = 0; r < 4; r++) {
            int idx = (b - 256) * 1024 + r * 256 + tid;  // < 4096
            int c = idx >> 5, e0 = (idx & 31) * 2;
            float x0 = WV[c * 64 + e0], x1 = WV[c * 64 + e0 + 1];
            __nv_bfloat16 h0 = __float2bfloat16(x0), h1 = __float2bfloat16(x1);
            __nv_bfloat162 hp = __halves2bfloat162(h0, h1);
            g_WVh[idx] = *(u32*)&hp;
        }
    }
}

// =================== qk = h_x @ Mfold (unroll 16) ===================
__global__ __launch_bounds__(256)
void qk_kernel(const float* __restrict__ hx) {
    __shared__ float sx[8][256];
    const int tid = threadIdx.x, r0 = blockIdx.x * 8;
    for (int i = tid; i < 2048; i += 256) sx[i >> 8][i & 255] = hx[r0 * 256 + i];
    __syncthreads();
    float a[8] = {0.f, 0.f, 0.f, 0.f, 0.f, 0.f, 0.f, 0.f};
    #pragma unroll 16
    for (int x = 0; x < 256; x++) {
        float mf = g_Mfold[x * 256 + tid];
        #pragma unroll
        for (int k = 0; k < 8; k++) a[k] += sx[k][x] * mf;
    }
    #pragma unroll
    for (int k = 0; k < 8; k++) g_qk[(r0 + k) * 256 + tid] = a[k];
}

// =================== main: batch-4 LDG pipelining, 4 CTAs/SM ===========
#define DYN_SMEM 32768

__global__ __launch_bounds__(256, 4)
void main_kernel(const float* __restrict__ h_e, const float* __restrict__ h_m) {
    extern __shared__ u32 dynu[];
    __shared__ __align__(16) float s_qk[256];
    __shared__ float s_attn[1024];
    __shared__ float s_asum[4];
    __shared__ float s_ps[2][128];
    __shared__ float s_pm[2][128];

    u32* s_bhi = dynu;           // [256 m][32 u32], rotation-swizzled

    const int bn   = blockIdx.x;
    const int tid  = threadIdx.x;
    const int wid  = tid >> 5;
    const int lane = tid & 31;
    const int gid  = lane >> 2;
    const int tid4 = lane & 3;
    const int cg   = wid & 3;    // c-group = head
    const int mh   = wid >> 2;   // m-half
    const int cbase = cg * 32;

    if (tid < 4) s_asum[tid] = 0.f;
    s_qk[tid] = g_qk[bn * 256 + tid];
    const float maskv = h_m[bn];
    __syncthreads();

    // qk weights for this thread's constant e-chunk, all 4 heads
    const int e0 = (tid & 15) * 4;
    float qkr[16];
    #pragma unroll
    for (int h = 0; h < 4; h++) {
        float4 q = *(const float4*)(s_qk + h * 64 + e0);
        qkr[h * 4 + 0] = q.x; qkr[h * 4 + 1] = q.y;
        qkr[h * 4 + 2] = q.z; qkr[h * 4 + 3] = q.w;
    }
    const int c0 = (tid & 15) * 2;   // constant bf16x2 col pair

    // ---- convert h_e -> bf16 hi smem + fused fp32 partial scores ----
    // batch-4 loads for MLP, then process
    const float4* src = (const float4*)(h_e + (size_t)bn * 16384);
    #pragma unroll
    for (int g = 0; g < 4; g++) {
        float4 vv[4];
        #pragma unroll
        for (int u = 0; u < 4; u++)
            vv[u] = src[(g * 4 + u) * 256 + tid];
        #pragma unroll
        for (int u = 0; u < 4; u++) {
            int flat = (g * 4 + u) * 256 + tid;
            int m = flat >> 4;
            float4 v = vv[u];
            __nv_bfloat16 b0 = __float2bfloat16(v.x), b1 = __float2bfloat16(v.y);
            __nv_bfloat16 b2 = __float2bfloat16(v.z), b3 = __float2bfloat16(v.w);
            __nv_bfloat162 h01 = __halves2bfloat162(b0, b1);
            __nv_bfloat162 h23 = __halves2bfloat162(b2, b3);
            u32 base = BP(m, c0);   // even, 8B-aligned; BP(m,c0+1)=base+1
            *(u64*)(s_bhi + base) = (u64)(*(u32*)&h01) | ((u64)(*(u32*)&h23) << 32);

            float p0 = v.x * qkr[0]  + v.y * qkr[1]  + v.z * qkr[2]  + v.w * qkr[3];
            float p1 = v.x * qkr[4]  + v.y * qkr[5]  + v.z * qkr[6]  + v.w * qkr[7];
            float p2 = v.x * qkr[8]  + v.y * qkr[9]  + v.z * qkr[10] + v.w * qkr[11];
            float p3 = v.x * qkr[12] + v.y * qkr[13] + v.z * qkr[14] + v.w * qkr[15];
            #pragma unroll
            for (int off = 1; off < 16; off <<= 1) {
                p0 += __shfl_xor_sync(0xffffffffu, p0, off);
                p1 += __shfl_xor_sync(0xffffffffu, p1, off);
                p2 += __shfl_xor_sync(0xffffffffu, p2, off);
                p3 += __shfl_xor_sync(0xffffffffu, p3, off);
            }
            if ((tid & 15) == 0) {
                s_attn[m]       = p0;
                s_attn[256 + m] = p1;
                s_attn[512 + m] = p2;
                s_attn[768 + m] = p3;
            }
        }
    }

    // ---- A fragments (W_V hi) -> registers, 2 c-tiles per warp ----
    u32 Ah[2][16];
    #pragma unroll
    for (int j = 0; j < 2; j++) {
        int r0 = cbase + j * 16 + gid;
        #pragma unroll
        for (int ks = 0; ks < 4; ks++) {
            int b0 = r0 * 32 + ks * 8 + tid4;
            int b1 = (r0 + 8) * 32 + ks * 8 + tid4;
            Ah[j][ks * 4 + 0] = g_WVh[b0];
            Ah[j][ks * 4 + 1] = g_WVh[b1];
            Ah[j][ks * 4 + 2] = g_WVh[b0 + 4];
            Ah[j][ks * 4 + 3] = g_WVh[b1 + 4];
        }
    }
    __syncthreads();

    // ---- softmax over heads (thread = m) ----
    {
        const int m = tid;
        float s0 = s_attn[m],       s1 = s_attn[256 + m];
        float s2 = s_attn[512 + m], s3 = s_attn[768 + m];
        if (maskv == 0.f) {
            const float ninf = __int_as_float(0xff800000);
            s0 = s1 = s2 = s3 = ninf;
        }
        float mx = fmaxf(fmaxf(s0, s1), fmaxf(s2, s3));
        float e0f = __expf(s0 - mx), e1f = __expf(s1 - mx);
        float e2f = __expf(s2 - mx), e3f = __expf(s3 - mx);
        float r  = 1.f / (e0f + e1f + e2f + e3f);
        float a0 = e0f * r, a1 = e1f * r, a2 = e2f * r, a3 = e3f * r;
        s_attn[m]       = a0;
        s_attn[256 + m] = a1;
        s_attn[512 + m] = a2;
        s_attn[768 + m] = a3;
        float t0 = a0, t1 = a1, t2 = a2, t3 = a3;
        #pragma unroll
        for (int off = 16; off; off >>= 1) {
            t0 += __shfl_xor_sync(0xffffffffu, t0, off);
            t1 += __shfl_xor_sync(0xffffffffu, t1, off);
            t2 += __shfl_xor_sync(0xffffffffu, t2, off);
            t3 += __shfl_xor_sync(0xffffffffu, t3, off);
        }
        if (lane == 0) {
            atomicAdd(&s_asum[0], t0);
            atomicAdd(&s_asum[1], t1);
            atomicAdd(&s_asum[2], t2);
            atomicAdd(&s_asum[3], t3);
        }
    }
    __syncthreads();

    // ---- mainloop: 16 m-tiles x 2 c-tiles, 1-term Ah*Bh ----
    const float ninf = __int_as_float(0xff800000);
    float sum0 = 0.f, sum1 = 0.f, sum2 = 0.f, sum3 = 0.f;
    float mx0 = ninf, mx1 = ninf, mx2 = ninf, mx3 = ninf;
    const float* ap = s_attn + cg * 256;

    for (int t = 0; t < 16; t++) {
        const int mbase = mh * 128 + t * 8;
        const int mrow  = mbase + gid;
        u32 Bh[8];
        #pragma unroll
        for (int ks = 0; ks < 4; ks++) {
            int cc = ks * 8 + tid4;
            Bh[ks * 2]     = s_bhi[BP(mrow, cc)];
            Bh[ks * 2 + 1] = s_bhi[BP(mrow, cc + 4)];
        }
        float2 at = *(const float2*)(ap + mbase + 2 * tid4);
        #pragma unroll
        for (int j = 0; j < 2; j++) {
            float d[4] = {0.f, 0.f, 0.f, 0.f};
            #pragma unroll
            for (int ks = 0; ks < 4; ks++)
                mma16816(d, &Ah[j][ks * 4], &Bh[ks * 2]);
            float w0 = at.x * d[0], w1 = at.y * d[1];
            float w2 = at.x * d[2], w3 = at.y * d[3];
            if (j == 0) {
                sum0 += w0 + w1; sum1 += w2 + w3;
                mx0 = fmaxf(mx0, fmaxf(w0, w1));
                mx1 = fmaxf(mx1, fmaxf(w2, w3));
            } else {
                sum2 += w0 + w1; sum3 += w2 + w3;
                mx2 = fmaxf(mx2, fmaxf(w0, w1));
                mx3 = fmaxf(mx3, fmaxf(w2, w3));
            }
        }
    }

    // reduce across quad (tid4)
    #pragma unroll
    for (int off = 1; off <= 2; off <<= 1) {
        sum0 += __shfl_xor_sync(0xffffffffu, sum0, off);
        sum1 += __shfl_xor_sync(0xffffffffu, sum1, off);
        sum2 += __shfl_xor_sync(0xffffffffu, sum2, off);
        sum3 += __shfl_xor_sync(0xffffffffu, sum3, off);
        mx0 = fmaxf(mx0, __shfl_xor_sync(0xffffffffu, mx0, off));
        mx1 = fmaxf(mx1, __shfl_xor_sync(0xffffffffu, mx1, off));
        mx2 = fmaxf(mx2, __shfl_xor_sync(0xffffffffu, mx2, off));
        mx3 = fmaxf(mx3, __shfl_xor_sync(0xffffffffu, mx3, off));
    }
    if (tid4 == 0) {
        s_ps[mh][cbase + gid]      = sum0;  s_pm[mh][cbase + gid]      = mx0;
        s_ps[mh][cbase + gid + 8]  = sum1;  s_pm[mh][cbase + gid + 8]  = mx1;
        s_ps[mh][cbase + gid + 16] = sum2;  s_pm[mh][cbase + gid + 16] = mx2;
        s_ps[mh][cbase + gid + 24] = sum3;  s_pm[mh][cbase + gid + 24] = mx3;
    }
    __syncthreads();

    if (tid < 128) {
        const int c = tid, h = c >> 5, d = c & 31;
        float s  = s_ps[0][c] + s_ps[1][c];
        float mx = fmaxf(s_pm[0][c], s_pm[1][c]);
        float asum = s_asum[h] + 1e-8f;
        float* mrow = g_multi + (size_t)bn * AGG + h * 65;
        mrow[d]      = s / asum;
        if (d == 0) mrow[32] = asum;
        mrow[33 + d] = mx;
    }
}

// =================== out v7: 512 threads, k split in 4 quarters ==============
// grid 256 x 512; 4 rows/block; thread = (o in [0,128), kq in {0..3})
// k ranges: [0,64) [64,128) [128,192) [192,260)
__global__ __launch_bounds__(512)
void out_kernel(const float* __restrict__ W_R, float* __restrict__ out) {
    __shared__ __align__(16) float smt[AGG][4];   // multi^T for 4 rows
    __shared__ float s_part[3][4][128];

    const int tid  = threadIdx.x;
    const int row0 = blockIdx.x * 4;

    for (int i = tid; i < 4 * AGG; i += 512) {
        int r = i / AGG, k = i - r * AGG;
        smt[k][r] = g_multi[(size_t)(row0 + r) * AGG + k];
    }
    __syncthreads();

    const int o  = tid & 127;
    const int kq = tid >> 7;          // 0..3
    const int kb = kq * 64;           // element-aligned to 4 floats
    const int nk = (kq == 3) ? 17 : 16;   // float4 count (last quarter: 68 floats)
    const float4* wr4 = (const float4*)(W_R + o * AGG + kb);
    float a0 = 0.f, a1 = 0.f, a2 = 0.f, a3 = 0.f;
    #pragma unroll 4
    for (int j = 0; j < nk; j++) {
        float4 w  = wr4[j];
        int k = kb + 4 * j;
        float4 m0 = *(const float4*)smt[k];
        float4 m1 = *(const float4*)smt[k + 1];
        float4 m2 = *(const float4*)smt[k + 2];
        float4 m3 = *(const float4*)smt[k + 3];
        a0 += m0.x * w.x + m1.x * w.y + m2.x * w.z + m3.x * w.w;
        a1 += m0.y * w.x + m1.y * w.y + m2.y * w.z + m3.y * w.w;
        a2 += m0.z * w.x + m1.z * w.y + m2.z * w.z + m3.z * w.w;
        a3 += m0.w * w.x + m1.w * w.y + m2.w * w.z + m3.w * w.w;
    }
    if (kq) {
        s_part[kq - 1][0][o] = a0; s_part[kq - 1][1][o] = a1;
        s_part[kq - 1][2][o] = a2; s_part[kq - 1][3][o] = a3;
    }
    __syncthreads();
    if (kq == 0) {
        out[(size_t)(row0 + 0) * 128 + o] = a0 + s_part[0][0][o] + s_part[1][0][o] + s_part[2][0][o];
        out[(size_t)(row0 + 1) * 128 + o] = a1 + s_part[0][1][o] + s_part[1][1][o] + s_part[2][1][o];
        out[(size_t)(row0 + 2) * 128 + o] = a2 + s_part[0][2][o] + s_part[1][2][o] + s_part[2][2][o];
        out[(size_t)(row0 + 3) * 128 + o] = a3 + s_part[0][3][o] + s_part[1][3][o] + s_part[2][3][o];
    }
}

// =================== launch ===================
extern "C" void kernel_launch(void* const* d_in, const int* in_sizes, int n_in,
                              void* d_out, int out_size) {
    (void)in_sizes; (void)n_in; (void)out_size;
    const float* h_x = (const float*)d_in[0];
    const float* h_e = (const float*)d_in[1];
    const float* h_m = (const float*)d_in[2];
    const float* W_Q = (const float*)d_in[3];
    const float* W_K = (const float*)d_in[4];
    const float* W_V = (const float*)d_in[5];
    const float* W_R = (const float*)d_in[6];
    float* out = (float*)d_out;

    cudaFuncSetAttribute(main_kernel,
                         cudaFuncAttributeMaxDynamicSharedMemorySize, DYN_SMEM);

    prep_kernel<<<260, 256>>>(W_Q, W_K, W_V);
    qk_kernel<<<128, 256>>>(h_x);
    main_kernel<<<ROWS, 256, DYN_SMEM>>>(h_e, h_m);
    out_kernel<<<256, 512>>>(W_R, out);
}

// round 14
// speedup vs baseline: 1.5771x; 1.0090x over previous
#include <cuda_runtime.h>
#include <cuda_bf16.h>
#include <cstdint>

typedef unsigned int       u32;
typedef unsigned long long u64;

#define ROWS 1024
#define AGG  260

__device__ float g_Mfold[256 * 256];   // [x][h*64+e], 1/sqrt(D) folded
__device__ float g_qk[ROWS * 256];
__device__ u32   g_WVh[4096];          // W_V hi bf16x2, [c*32 + e/2]
__device__ float g_WRt[AGG * 128];     // W_R transposed [k][o]
__device__ float g_multi[ROWS * AGG];

// ---------------- warp mma: m16n8k16 bf16, D/C f32, accumulate in-place ----
__device__ __forceinline__ void mma16816(float* d, const u32* a, const u32* b) {
    asm volatile(
        "mma.sync.aligned.m16n8k16.row.col.f32.bf16.bf16.f32 "
        "{%0,%1,%2,%3}, {%4,%5,%6,%7}, {%8,%9}, {%0,%1,%2,%3};"
        : "+f"(d[0]), "+f"(d[1]), "+f"(d[2]), "+f"(d[3])
        : "r"(a[0]), "r"(a[1]), "r"(a[2]), "r"(a[3]), "r"(b[0]), "r"(b[1]));
}

// rotation swizzle: row m (32 u32), logical col c -> conflict-free banks
#define BP(m, c) ((m) * 32 + (((c) + ((m) << 2)) & 31))

// =================== prep: Mfold + W_V bf16 hi + W_R transpose ===========
__global__ __launch_bounds__(256)
void prep_kernel(const float* __restrict__ WQ, const float* __restrict__ WK,
                 const float* __restrict__ WV, const float* __restrict__ WR) {
    const int b = blockIdx.x, tid = threadIdx.x;
    if (b < 256) {
        __shared__ float wq[128];
        if (tid < 128) wq[tid] = WQ[tid * 256 + b];
        __syncthreads();
        const int h = tid >> 6, e = tid & 63;
        float acc = 0.f;
        #pragma unroll 8
        for (int d = 0; d < 32; d++)
            acc += wq[h * 32 + d] * WK[(h * 32 + d) * 64 + e];
        g_Mfold[b * 256 + tid] = acc * 0.1767766952966369f;  // 1/sqrt(32)
    } else if (b < 260) {
        #pragma unroll
        for (int r = 0; r < 4; r++) {
            int idx = (b - 256) * 1024 + r * 256 + tid;  // < 4096
            int c = idx >> 5, e0 = (idx & 31) * 2;
            float x0 = WV[c * 64 + e0], x1 = WV[c * 64 + e0 + 1];
            __nv_bfloat16 h0 = __float2bfloat16(x0), h1 = __float2bfloat16(x1);
            __nv_bfloat162 hp = __halves2bfloat162(h0, h1);
            g_WVh[idx] = *(u32*)&hp;
        }
    } else {
        int idx = (b - 260) * 256 + tid;             // < 33280 = 260*128
        int k = idx >> 7, o = idx & 127;
        g_WRt[idx] = WR[o * 260 + k];
    }
}

// =================== qk = h_x @ Mfold (unroll 16) ===================
__global__ __launch_bounds__(256)
void qk_kernel(const float* __restrict__ hx) {
    __shared__ float sx[8][256];
    const int tid = threadIdx.x, r0 = blockIdx.x * 8;
    for (int i = tid; i < 2048; i += 256) sx[i >> 8][i & 255] = hx[r0 * 256 + i];
    __syncthreads();
    float a[8] = {0.f, 0.f, 0.f, 0.f, 0.f, 0.f, 0.f, 0.f};
    #pragma unroll 16
    for (int x = 0; x < 256; x++) {
        float mf = g_Mfold[x * 256 + tid];
        #pragma unroll
        for (int k = 0; k < 8; k++) a[k] += sx[k][x] * mf;
    }
    #pragma unroll
    for (int k = 0; k < 8; k++) g_qk[(r0 + k) * 256 + tid] = a[k];
}

// =================== main: batch-4 LDG pipelining, 4 CTAs/SM (R13 exact) =====
#define DYN_SMEM 32768

__global__ __launch_bounds__(256, 4)
void main_kernel(const float* __restrict__ h_e, const float* __restrict__ h_m) {
    extern __shared__ u32 dynu[];
    __shared__ __align__(16) float s_qk[256];
    __shared__ float s_attn[1024];
    __shared__ float s_asum[4];
    __shared__ float s_ps[2][128];
    __shared__ float s_pm[2][128];

    u32* s_bhi = dynu;           // [256 m][32 u32], rotation-swizzled

    const int bn   = blockIdx.x;
    const int tid  = threadIdx.x;
    const int wid  = tid >> 5;
    const int lane = tid & 31;
    const int gid  = lane >> 2;
    const int tid4 = lane & 3;
    const int cg   = wid & 3;    // c-group = head
    const int mh   = wid >> 2;   // m-half
    const int cbase = cg * 32;

    if (tid < 4) s_asum[tid] = 0.f;
    s_qk[tid] = g_qk[bn * 256 + tid];
    const float maskv = h_m[bn];
    __syncthreads();

    // qk weights for this thread's constant e-chunk, all 4 heads
    const int e0 = (tid & 15) * 4;
    float qkr[16];
    #pragma unroll
    for (int h = 0; h < 4; h++) {
        float4 q = *(const float4*)(s_qk + h * 64 + e0);
        qkr[h * 4 + 0] = q.x; qkr[h * 4 + 1] = q.y;
        qkr[h * 4 + 2] = q.z; qkr[h * 4 + 3] = q.w;
    }
    const int c0 = (tid & 15) * 2;   // constant bf16x2 col pair

    // ---- convert h_e -> bf16 hi smem + fused fp32 partial scores ----
    const float4* src = (const float4*)(h_e + (size_t)bn * 16384);
    #pragma unroll
    for (int g = 0; g < 4; g++) {
        float4 vv[4];
        #pragma unroll
        for (int u = 0; u < 4; u++)
            vv[u] = src[(g * 4 + u) * 256 + tid];
        #pragma unroll
        for (int u = 0; u < 4; u++) {
            int flat = (g * 4 + u) * 256 + tid;
            int m = flat >> 4;
            float4 v = vv[u];
            __nv_bfloat16 b0 = __float2bfloat16(v.x), b1 = __float2bfloat16(v.y);
            __nv_bfloat16 b2 = __float2bfloat16(v.z), b3 = __float2bfloat16(v.w);
            __nv_bfloat162 h01 = __halves2bfloat162(b0, b1);
            __nv_bfloat162 h23 = __halves2bfloat162(b2, b3);
            u32 base = BP(m, c0);   // even, 8B-aligned; BP(m,c0+1)=base+1
            *(u64*)(s_bhi + base) = (u64)(*(u32*)&h01) | ((u64)(*(u32*)&h23) << 32);

            float p0 = v.x * qkr[0]  + v.y * qkr[1]  + v.z * qkr[2]  + v.w * qkr[3];
            float p1 = v.x * qkr[4]  + v.y * qkr[5]  + v.z * qkr[6]  + v.w * qkr[7];
            float p2 = v.x * qkr[8]  + v.y * qkr[9]  + v.z * qkr[10] + v.w * qkr[11];
            float p3 = v.x * qkr[12] + v.y * qkr[13] + v.z * qkr[14] + v.w * qkr[15];
            #pragma unroll
            for (int off = 1; off < 16; off <<= 1) {
                p0 += __shfl_xor_sync(0xffffffffu, p0, off);
                p1 += __shfl_xor_sync(0xffffffffu, p1, off);
                p2 += __shfl_xor_sync(0xffffffffu, p2, off);
                p3 += __shfl_xor_sync(0xffffffffu, p3, off);
            }
            if ((tid & 15) == 0) {
                s_attn[m]       = p0;
                s_attn[256 + m] = p1;
                s_attn[512 + m] = p2;
                s_attn[768 + m] = p3;
            }
        }
    }

    // ---- A fragments (W_V hi) -> registers, 2 c-tiles per warp ----
    u32 Ah[2][16];
    #pragma unroll
    for (int j = 0; j < 2; j++) {
        int r0 = cbase + j * 16 + gid;
        #pragma unroll
        for (int ks = 0; ks < 4; ks++) {
            int b0 = r0 * 32 + ks * 8 + tid4;
            int b1 = (r0 + 8) * 32 + ks * 8 + tid4;
            Ah[j][ks * 4 + 0] = g_WVh[b0];
            Ah[j][ks * 4 + 1] = g_WVh[b1];
            Ah[j][ks * 4 + 2] = g_WVh[b0 + 4];
            Ah[j][ks * 4 + 3] = g_WVh[b1 + 4];
        }
    }
    __syncthreads();

    // ---- softmax over heads (thread = m) ----
    {
        const int m = tid;
        float s0 = s_attn[m],       s1 = s_attn[256 + m];
        float s2 = s_attn[512 + m], s3 = s_attn[768 + m];
        if (maskv == 0.f) {
            const float ninf = __int_as_float(0xff800000);
            s0 = s1 = s2 = s3 = ninf;
        }
        float mx = fmaxf(fmaxf(s0, s1), fmaxf(s2, s3));
        float e0f = __expf(s0 - mx), e1f = __expf(s1 - mx);
        float e2f = __expf(s2 - mx), e3f = __expf(s3 - mx);
        float r  = 1.f / (e0f + e1f + e2f + e3f);
        float a0 = e0f * r, a1 = e1f * r, a2 = e2f * r, a3 = e3f * r;
        s_attn[m]       = a0;
        s_attn[256 + m] = a1;
        s_attn[512 + m] = a2;
        s_attn[768 + m] = a3;
        float t0 = a0, t1 = a1, t2 = a2, t3 = a3;
        #pragma unroll
        for (int off = 16; off; off >>= 1) {
            t0 += __shfl_xor_sync(0xffffffffu, t0, off);
            t1 += __shfl_xor_sync(0xffffffffu, t1, off);
            t2 += __shfl_xor_sync(0xffffffffu, t2, off);
            t3 += __shfl_xor_sync(0xffffffffu, t3, off);
        }
        if (lane == 0) {
            atomicAdd(&s_asum[0], t0);
            atomicAdd(&s_asum[1], t1);
            atomicAdd(&s_asum[2], t2);
            atomicAdd(&s_asum[3], t3);
        }
    }
    __syncthreads();

    // ---- mainloop: 16 m-tiles x 2 c-tiles, 1-term Ah*Bh ----
    const float ninf = __int_as_float(0xff800000);
    float sum0 = 0.f, sum1 = 0.f, sum2 = 0.f, sum3 = 0.f;
    float mx0 = ninf, mx1 = ninf, mx2 = ninf, mx3 = ninf;
    const float* ap = s_attn + cg * 256;

    for (int t = 0; t < 16; t++) {
        const int mbase = mh * 128 + t * 8;
        const int mrow  = mbase + gid;
        u32 Bh[8];
        #pragma unroll
        for (int ks = 0; ks < 4; ks++) {
            int cc = ks * 8 + tid4;
            Bh[ks * 2]     = s_bhi[BP(mrow, cc)];
            Bh[ks * 2 + 1] = s_bhi[BP(mrow, cc + 4)];
        }
        float2 at = *(const float2*)(ap + mbase + 2 * tid4);
        #pragma unroll
        for (int j = 0; j < 2; j++) {
            float d[4] = {0.f, 0.f, 0.f, 0.f};
            #pragma unroll
            for (int ks = 0; ks < 4; ks++)
                mma16816(d, &Ah[j][ks * 4], &Bh[ks * 2]);
            float w0 = at.x * d[0], w1 = at.y * d[1];
            float w2 = at.x * d[2], w3 = at.y * d[3];
            if (j == 0) {
                sum0 += w0 + w1; sum1 += w2 + w3;
                mx0 = fmaxf(mx0, fmaxf(w0, w1));
                mx1 = fmaxf(mx1, fmaxf(w2, w3));
            } else {
                sum2 += w0 + w1; sum3 += w2 + w3;
                mx2 = fmaxf(mx2, fmaxf(w0, w1));
                mx3 = fmaxf(mx3, fmaxf(w2, w3));
            }
        }
    }

    // reduce across quad (tid4)
    #pragma unroll
    for (int off = 1; off <= 2; off <<= 1) {
        sum0 += __shfl_xor_sync(0xffffffffu, sum0, off);
        sum1 += __shfl_xor_sync(0xffffffffu, sum1, off);
        sum2 += __shfl_xor_sync(0xffffffffu, sum2, off);
        sum3 += __shfl_xor_sync(0xffffffffu, sum3, off);
        mx0 = fmaxf(mx0, __shfl_xor_sync(0xffffffffu, mx0, off));
        mx1 = fmaxf(mx1, __shfl_xor_sync(0xffffffffu, mx1, off));
        mx2 = fmaxf(mx2, __shfl_xor_sync(0xffffffffu, mx2, off));
        mx3 = fmaxf(mx3, __shfl_xor_sync(0xffffffffu, mx3, off));
    }
    if (tid4 == 0) {
        s_ps[mh][cbase + gid]      = sum0;  s_pm[mh][cbase + gid]      = mx0;
        s_ps[mh][cbase + gid + 8]  = sum1;  s_pm[mh][cbase + gid + 8]  = mx1;
        s_ps[mh][cbase + gid + 16] = sum2;  s_pm[mh][cbase + gid + 16] = mx2;
        s_ps[mh][cbase + gid + 24] = sum3;  s_pm[mh][cbase + gid + 24] = mx3;
    }
    __syncthreads();

    if (tid < 128) {
        const int c = tid, h = c >> 5, d = c & 31;
        float s  = s_ps[0][c] + s_ps[1][c];
        float mx = fmaxf(s_pm[0][c], s_pm[1][c]);
        float asum = s_asum[h] + 1e-8f;
        float* mrow = g_multi + (size_t)bn * AGG + h * 65;
        mrow[d]      = s / asum;
        if (d == 0) mrow[32] = asum;
        mrow[33 + d] = mx;
    }
}

// =================== out v8: v7 structure + coalesced g_WRt stream ===========
// grid 256 x 512; 4 rows/block; thread = (o in [0,128), kq in {0..3})
// k ranges: [0,64) [64,128) [128,192) [192,260)
__global__ __launch_bounds__(512)
void out_kernel(float* __restrict__ out) {
    __shared__ __align__(16) float smt[AGG][4];   // multi^T for 4 rows
    __shared__ float s_part[3][4][128];

    const int tid  = threadIdx.x;
    const int row0 = blockIdx.x * 4;

    for (int i = tid; i < 4 * AGG; i += 512) {
        int r = i / AGG, k = i - r * AGG;
        smt[k][r] = g_multi[(size_t)(row0 + r) * AGG + k];
    }
    __syncthreads();

    const int o  = tid & 127;
    const int kq = tid >> 7;          // 0..3
    const int kb = kq * 64;
    const int nk = (kq == 3) ? 68 : 64;
    const float* wr = g_WRt + kb * 128 + o;   // coalesced across o (lane-consecutive)
    float a0 = 0.f, a1 = 0.f, a2 = 0.f, a3 = 0.f;
    #pragma unroll 16
    for (int k = 0; k < nk; k++) {
        float w  = wr[k * 128];
        float4 m = *(const float4*)smt[kb + k];
        a0 += m.x * w; a1 += m.y * w; a2 += m.z * w; a3 += m.w * w;
    }
    if (kq) {
        s_part[kq - 1][0][o] = a0; s_part[kq - 1][1][o] = a1;
        s_part[kq - 1][2][o] = a2; s_part[kq - 1][3][o] = a3;
    }
    __syncthreads();
    if (kq == 0) {
        out[(size_t)(row0 + 0) * 128 + o] = a0 + s_part[0][0][o] + s_part[1][0][o] + s_part[2][0][o];
        out[(size_t)(row0 + 1) * 128 + o] = a1 + s_part[0][1][o] + s_part[1][1][o] + s_part[2][1][o];
        out[(size_t)(row0 + 2) * 128 + o] = a2 + s_part[0][2][o] + s_part[1][2][o] + s_part[2][2][o];
        out[(size_t)(row0 + 3) * 128 + o] = a3 + s_part[0][3][o] + s_part[1][3][o] + s_part[2][3][o];
    }
}

// =================== launch ===================
extern "C" void kernel_launch(void* const* d_in, const int* in_sizes, int n_in,
                              void* d_out, int out_size) {
    (void)in_sizes; (void)n_in; (void)out_size;
    const float* h_x = (const float*)d_in[0];
    const float* h_e = (const float*)d_in[1];
    const float* h_m = (const float*)d_in[2];
    const float* W_Q = (const float*)d_in[3];
    const float* W_K = (const float*)d_in[4];
    const float* W_V = (const float*)d_in[5];
    const float* W_R = (const float*)d_in[6];
    float* out = (float*)d_out;

    cudaFuncSetAttribute(main_kernel,
                         cudaFuncAttributeMaxDynamicSharedMemorySize, DYN_SMEM);

    prep_kernel<<<390, 256>>>(W_Q, W_K, W_V, W_R);
    qk_kernel<<<128, 256>>>(h_x);
    main_kernel<<<ROWS, 256, DYN_SMEM>>>(h_e, h_m);
    out_kernel<<<256, 512>>>(out);
}

// round 15
// speedup vs baseline: 1.6841x; 1.0679x over previous
#include <cuda_runtime.h>
#include <cuda_bf16.h>
#include <cstdint>

typedef unsigned int       u32;
typedef unsigned long long u64;

#define ROWS 1024
#define AGG  260

__device__ float g_Mfold[256 * 256];   // [x][h*64+e], 1/sqrt(D) folded
__device__ float g_qk[ROWS * 256];
__device__ u32   g_WVh[4096];          // W_V hi bf16x2, [c*32 + e/2]
__device__ float g_WRt[AGG * 128];     // W_R transposed [k][o]
__device__ float g_multi[ROWS * AGG];

// ---------------- warp mma: m16n8k16 bf16, D/C f32, accumulate in-place ----
__device__ __forceinline__ void mma16816(float* d, const u32* a, const u32* b) {
    asm volatile(
        "mma.sync.aligned.m16n8k16.row.col.f32.bf16.bf16.f32 "
        "{%0,%1,%2,%3}, {%4,%5,%6,%7}, {%8,%9}, {%0,%1,%2,%3};"
        : "+f"(d[0]), "+f"(d[1]), "+f"(d[2]), "+f"(d[3])
        : "r"(a[0]), "r"(a[1]), "r"(a[2]), "r"(a[3]), "r"(b[0]), "r"(b[1]));
}

// rotation swizzle: row m (32 u32), logical col c -> conflict-free banks
#define BP(m, c) ((m) * 32 + (((c) + ((m) << 2)) & 31))

// =================== prep: Mfold + W_V bf16 hi + W_R transpose ===========
__global__ __launch_bounds__(256)
void prep_kernel(const float* __restrict__ WQ, const float* __restrict__ WK,
                 const float* __restrict__ WV, const float* __restrict__ WR) {
    const int b = blockIdx.x, tid = threadIdx.x;
    if (b < 256) {
        __shared__ float wq[128];
        if (tid < 128) wq[tid] = WQ[tid * 256 + b];
        __syncthreads();
        const int h = tid >> 6, e = tid & 63;
        float acc = 0.f;
        #pragma unroll 8
        for (int d = 0; d < 32; d++)
            acc += wq[h * 32 + d] * WK[(h * 32 + d) * 64 + e];
        g_Mfold[b * 256 + tid] = acc * 0.1767766952966369f;  // 1/sqrt(32)
    } else if (b < 260) {
        #pragma unroll
        for (int r = 0; r < 4; r++) {
            int idx = (b - 256) * 1024 + r * 256 + tid;  // < 4096
            int c = idx >> 5, e0 = (idx & 31) * 2;
            float x0 = WV[c * 64 + e0], x1 = WV[c * 64 + e0 + 1];
            __nv_bfloat16 h0 = __float2bfloat16(x0), h1 = __float2bfloat16(x1);
            __nv_bfloat162 hp = __halves2bfloat162(h0, h1);
            g_WVh[idx] = *(u32*)&hp;
        }
    } else {
        int idx = (b - 260) * 256 + tid;             // < 33280 = 260*128
        int k = idx >> 7, o = idx & 127;
        g_WRt[idx] = WR[o * 260 + k];
    }
}

// =================== qk = h_x @ Mfold (unroll 16) ===================
__global__ __launch_bounds__(256)
void qk_kernel(const float* __restrict__ hx) {
    __shared__ float sx[8][256];
    const int tid = threadIdx.x, r0 = blockIdx.x * 8;
    for (int i = tid; i < 2048; i += 256) sx[i >> 8][i & 255] = hx[r0 * 256 + i];
    __syncthreads();
    float a[8] = {0.f, 0.f, 0.f, 0.f, 0.f, 0.f, 0.f, 0.f};
    #pragma unroll 16
    for (int x = 0; x < 256; x++) {
        float mf = g_Mfold[x * 256 + tid];
        #pragma unroll
        for (int k = 0; k < 8; k++) a[k] += sx[k][x] * mf;
    }
    #pragma unroll
    for (int k = 0; k < 8; k++) g_qk[(r0 + k) * 256 + tid] = a[k];
}

// =================== main: scores via HMMA (no shuffle reduction) ============
#define DYN_SMEM 32768

__global__ __launch_bounds__(256, 4)
void main_kernel(const float* __restrict__ h_e, const float* __restrict__ h_m) {
    extern __shared__ u32 dynu[];
    __shared__ __align__(16) float s_qk[256];
    __shared__ __align__(8) u32 s_qkb[4][32];   // qk bf16x2 [h][e-pair]
    __shared__ float s_attn[1024];
    __shared__ float s_asum[4];
    __shared__ float s_ps[2][128];
    __shared__ float s_pm[2][128];

    u32* s_bhi = dynu;           // [256 m][32 u32], rotation-swizzled

    const int bn   = blockIdx.x;
    const int tid  = threadIdx.x;
    const int wid  = tid >> 5;
    const int lane = tid & 31;
    const int gid  = lane >> 2;
    const int tid4 = lane & 3;
    const int cg   = wid & 3;    // c-group = head
    const int mh   = wid >> 2;   // m-half
    const int cbase = cg * 32;

    if (tid < 4) s_asum[tid] = 0.f;
    s_qk[tid] = g_qk[bn * 256 + tid];
    const float maskv = h_m[bn];
    __syncthreads();

    // build qk bf16 fragments source
    if (tid < 128) {
        int h = tid >> 5, p = tid & 31;
        __nv_bfloat162 q = __floats2bfloat162_rn(s_qk[h * 64 + 2 * p],
                                                 s_qk[h * 64 + 2 * p + 1]);
        s_qkb[h][p] = *(u32*)&q;
    }

    const int c0 = (tid & 15) * 2;   // constant bf16x2 col pair

    // ---- convert h_e -> bf16 hi smem (pure, batch-4 LDG) ----
    const float4* src = (const float4*)(h_e + (size_t)bn * 16384);
    #pragma unroll
    for (int g = 0; g < 4; g++) {
        float4 vv[4];
        #pragma unroll
        for (int u = 0; u < 4; u++)
            vv[u] = src[(g * 4 + u) * 256 + tid];
        #pragma unroll
        for (int u = 0; u < 4; u++) {
            int m = ((g * 4 + u) * 256 + tid) >> 4;
            float4 v = vv[u];
            __nv_bfloat162 h01 = __floats2bfloat162_rn(v.x, v.y);
            __nv_bfloat162 h23 = __floats2bfloat162_rn(v.z, v.w);
            u32 base = BP(m, c0);   // even, 8B-aligned; BP(m,c0+1)=base+1
            *(u64*)(s_bhi + base) = (u64)(*(u32*)&h01) | ((u64)(*(u32*)&h23) << 32);
        }
    }

    // ---- A fragments (W_V hi) -> registers, 2 c-tiles per warp ----
    u32 Ah[2][16];
    #pragma unroll
    for (int j = 0; j < 2; j++) {
        int r0 = cbase + j * 16 + gid;
        #pragma unroll
        for (int ks = 0; ks < 4; ks++) {
            int b0 = r0 * 32 + ks * 8 + tid4;
            int b1 = (r0 + 8) * 32 + ks * 8 + tid4;
            Ah[j][ks * 4 + 0] = g_WVh[b0];
            Ah[j][ks * 4 + 1] = g_WVh[b1];
            Ah[j][ks * 4 + 2] = g_WVh[b0 + 4];
            Ah[j][ks * 4 + 3] = g_WVh[b1 + 4];
        }
    }
    __syncthreads();

    // ---- scores via HMMA: D[h, m] = qk(bf16) x bhi^T; warp covers 32 m ----
    {
        u32 aqk[4][4];
        #pragma unroll
        for (int ks = 0; ks < 4; ks++) {
            u32 v0 = 0, v2 = 0;
            if (gid < 4) {
                v0 = s_qkb[gid][ks * 8 + tid4];
                v2 = s_qkb[gid][ks * 8 + tid4 + 4];
            }
            aqk[ks][0] = v0; aqk[ks][1] = 0;
            aqk[ks][2] = v2; aqk[ks][3] = 0;
        }
        #pragma unroll
        for (int nt = 0; nt < 4; nt++) {
            int mb = wid * 32 + nt * 8;
            float d[4] = {0.f, 0.f, 0.f, 0.f};
            #pragma unroll
            for (int ks = 0; ks < 4; ks++) {
                u32 B2[2];
                int cc = ks * 8 + tid4;
                B2[0] = s_bhi[BP(mb + gid, cc)];
                B2[1] = s_bhi[BP(mb + gid, cc + 4)];
                mma16816(d, aqk[ks], B2);
            }
            if (gid < 4) {
                int m = mb + 2 * tid4;
                *(float2*)(s_attn + gid * 256 + m) = make_float2(d[0], d[1]);
            }
        }
    }
    __syncthreads();

    // ---- softmax over heads (thread = m) ----
    {
        const int m = tid;
        float s0 = s_attn[m],       s1 = s_attn[256 + m];
        float s2 = s_attn[512 + m], s3 = s_attn[768 + m];
        if (maskv == 0.f) {
            const float ninf = __int_as_float(0xff800000);
            s0 = s1 = s2 = s3 = ninf;
        }
        float mx = fmaxf(fmaxf(s0, s1), fmaxf(s2, s3));
        float e0f = __expf(s0 - mx), e1f = __expf(s1 - mx);
        float e2f = __expf(s2 - mx), e3f = __expf(s3 - mx);
        float r  = 1.f / (e0f + e1f + e2f + e3f);
        float a0 = e0f * r, a1 = e1f * r, a2 = e2f * r, a3 = e3f * r;
        s_attn[m]       = a0;
        s_attn[256 + m] = a1;
        s_attn[512 + m] = a2;
        s_attn[768 + m] = a3;
        float t0 = a0, t1 = a1, t2 = a2, t3 = a3;
        #pragma unroll
        for (int off = 16; off; off >>= 1) {
            t0 += __shfl_xor_sync(0xffffffffu, t0, off);
            t1 += __shfl_xor_sync(0xffffffffu, t1, off);
            t2 += __shfl_xor_sync(0xffffffffu, t2, off);
            t3 += __shfl_xor_sync(0xffffffffu, t3, off);
        }
        if (lane == 0) {
            atomicAdd(&s_asum[0], t0);
            atomicAdd(&s_asum[1], t1);
            atomicAdd(&s_asum[2], t2);
            atomicAdd(&s_asum[3], t3);
        }
    }
    __syncthreads();

    // ---- mainloop: 16 m-tiles x 2 c-tiles, 1-term Ah*Bh ----
    const float ninf = __int_as_float(0xff800000);
    float sum0 = 0.f, sum1 = 0.f, sum2 = 0.f, sum3 = 0.f;
    float mx0 = ninf, mx1 = ninf, mx2 = ninf, mx3 = ninf;
    const float* ap = s_attn + cg * 256;

    for (int t = 0; t < 16; t++) {
        const int mbase = mh * 128 + t * 8;
        const int mrow  = mbase + gid;
        u32 Bh[8];
        #pragma unroll
        for (int ks = 0; ks < 4; ks++) {
            int cc = ks * 8 + tid4;
            Bh[ks * 2]     = s_bhi[BP(mrow, cc)];
            Bh[ks * 2 + 1] = s_bhi[BP(mrow, cc + 4)];
        }
        float2 at = *(const float2*)(ap + mbase + 2 * tid4);
        #pragma unroll
        for (int j = 0; j < 2; j++) {
            float d[4] = {0.f, 0.f, 0.f, 0.f};
            #pragma unroll
            for (int ks = 0; ks < 4; ks++)
                mma16816(d, &Ah[j][ks * 4], &Bh[ks * 2]);
            float w0 = at.x * d[0], w1 = at.y * d[1];
            float w2 = at.x * d[2], w3 = at.y * d[3];
            if (j == 0) {
                sum0 += w0 + w1; sum1 += w2 + w3;
                mx0 = fmaxf(mx0, fmaxf(w0, w1));
                mx1 = fmaxf(mx1, fmaxf(w2, w3));
            } else {
                sum2 += w0 + w1; sum3 += w2 + w3;
                mx2 = fmaxf(mx2, fmaxf(w0, w1));
                mx3 = fmaxf(mx3, fmaxf(w2, w3));
            }
        }
    }

    // reduce across quad (tid4)
    #pragma unroll
    for (int off = 1; off <= 2; off <<= 1) {
        sum0 += __shfl_xor_sync(0xffffffffu, sum0, off);
        sum1 += __shfl_xor_sync(0xffffffffu, sum1, off);
        sum2 += __shfl_xor_sync(0xffffffffu, sum2, off);
        sum3 += __shfl_xor_sync(0xffffffffu, sum3, off);
        mx0 = fmaxf(mx0, __shfl_xor_sync(0xffffffffu, mx0, off));
        mx1 = fmaxf(mx1, __shfl_xor_sync(0xffffffffu, mx1, off));
        mx2 = fmaxf(mx2, __shfl_xor_sync(0xffffffffu, mx2, off));
        mx3 = fmaxf(mx3, __shfl_xor_sync(0xffffffffu, mx3, off));
    }
    if (tid4 == 0) {
        s_ps[mh][cbase + gid]      = sum0;  s_pm[mh][cbase + gid]      = mx0;
        s_ps[mh][cbase + gid + 8]  = sum1;  s_pm[mh][cbase + gid + 8]  = mx1;
        s_ps[mh][cbase + gid + 16] = sum2;  s_pm[mh][cbase + gid + 16] = mx2;
        s_ps[mh][cbase + gid + 24] = sum3;  s_pm[mh][cbase + gid + 24] = mx3;
    }
    __syncthreads();

    if (tid < 128) {
        const int c = tid, h = c >> 5, d = c & 31;
        float s  = s_ps[0][c] + s_ps[1][c];
        float mx = fmaxf(s_pm[0][c], s_pm[1][c]);
        float asum = s_asum[h] + 1e-8f;
        float* mrow = g_multi + (size_t)bn * AGG + h * 65;
        mrow[d]      = s / asum;
        if (d == 0) mrow[32] = asum;
        mrow[33 + d] = mx;
    }
}

// =================== out v8 (R14 exact) ===================
__global__ __launch_bounds__(512)
void out_kernel(float* __restrict__ out) {
    __shared__ __align__(16) float smt[AGG][4];   // multi^T for 4 rows
    __shared__ float s_part[3][4][128];

    const int tid  = threadIdx.x;
    const int row0 = blockIdx.x * 4;

    for (int i = tid; i < 4 * AGG; i += 512) {
        int r = i / AGG, k = i - r * AGG;
        smt[k][r] = g_multi[(size_t)(row0 + r) * AGG + k];
    }
    __syncthreads();

    const int o  = tid & 127;
    const int kq = tid >> 7;          // 0..3
    const int kb = kq * 64;
    const int nk = (kq == 3) ? 68 : 64;
    const float* wr = g_WRt + kb * 128 + o;   // coalesced across o
    float a0 = 0.f, a1 = 0.f, a2 = 0.f, a3 = 0.f;
    #pragma unroll 16
    for (int k = 0; k < nk; k++) {
        float w  = wr[k * 128];
        float4 m = *(const float4*)smt[kb + k];
        a0 += m.x * w; a1 += m.y * w; a2 += m.z * w; a3 += m.w * w;
    }
    if (kq) {
        s_part[kq - 1][0][o] = a0; s_part[kq - 1][1][o] = a1;
        s_part[kq - 1][2][o] = a2; s_part[kq - 1][3][o] = a3;
    }
    __syncthreads();
    if (kq == 0) {
        out[(size_t)(row0 + 0) * 128 + o] = a0 + s_part[0][0][o] + s_part[1][0][o] + s_part[2][0][o];
        out[(size_t)(row0 + 1) * 128 + o] = a1 + s_part[0][1][o] + s_part[1][1][o] + s_part[2][1][o];
        out[(size_t)(row0 + 2) * 128 + o] = a2 + s_part[0][2][o] + s_part[1][2][o] + s_part[2][2][o];
        out[(size_t)(row0 + 3) * 128 + o] = a3 + s_part[0][3][o] + s_part[1][3][o] + s_part[2][3][o];
    }
}

// =================== launch ===================
extern "C" void kernel_launch(void* const* d_in, const int* in_sizes, int n_in,
                              void* d_out, int out_size) {
    (void)in_sizes; (void)n_in; (void)out_size;
    const float* h_x = (const float*)d_in[0];
    const float* h_e = (const float*)d_in[1];
    const float* h_m = (const float*)d_in[2];
    const float* W_Q = (const float*)d_in[3];
    const float* W_K = (const float*)d_in[4];
    const float* W_V = (const float*)d_in[5];
    const float* W_R = (const float*)d_in[6];
    float* out = (float*)d_out;

    cudaFuncSetAttribute(main_kernel,
                         cudaFuncAttributeMaxDynamicSharedMemorySize, DYN_SMEM);

    prep_kernel<<<390, 256>>>(W_Q, W_K, W_V, W_R);
    qk_kernel<<<128, 256>>>(h_x);
    main_kernel<<<ROWS, 256, DYN_SMEM>>>(h_e, h_m);
    out_kernel<<<256, 512>>>(out);
}